// round 6
// baseline (speedup 1.0000x reference)
#include <cuda_runtime.h>
#include <cuda_bf16.h>
#include <mma.h>
#include <stdint.h>

using namespace nvcuda;

#define B_  4
#define L_  2048
#define D_  1024
#define H_  16
#define DH_ 64
#define M_  (B_*L_)
#define BH_ (B_*H_)
#define SCALE 0.5f

typedef __nv_bfloat16 bf16;

// ---------------- static scratch ----------------
__device__ float g_O[(size_t)M_*D_];
__device__ bf16 g_Qh[(size_t)BH_*L_*DH_];
__device__ bf16 g_Ql[(size_t)BH_*L_*DH_];
__device__ bf16 g_Kh[(size_t)BH_*L_*DH_];
__device__ bf16 g_Kl[(size_t)BH_*L_*DH_];
__device__ bf16 g_Vh[(size_t)BH_*L_*DH_];
__device__ bf16 g_Vl[(size_t)BH_*L_*DH_];
__device__ bf16 g_Wth[4][(size_t)D_*D_];    // W^T hi: [n][k]
__device__ bf16 g_Wtl[4][(size_t)D_*D_];
__device__ float g_partial[(size_t)BH_*16*128*16];   // row-sum partials, 8MB
__device__ float g_attn_fallback[(size_t)BH_*L_*L_];

__device__ __forceinline__ void split1(float x, unsigned short& h, unsigned short& l){
    bf16 hb = __float2bfloat16(x);
    float r = x - __bfloat162float(hb);
    bf16 lb = __float2bfloat16(r);
    h = __bfloat16_as_ushort(hb);
    l = __bfloat16_as_ushort(lb);
}

// fp32 [128 rows x 32 k] -> split hi/lo bf16 smem tiles, pitch 48 elements
__device__ __forceinline__ void load_a_split(int tid, const float* __restrict__ X, int ldx,
                                             int row0, int k0, bf16* dh, bf16* dl){
    #pragma unroll
    for (int i = 0; i < 4; i++) {
        int e = tid + i*256;
        int m = e >> 3, k4 = (e & 7) << 2;
        float4 v = *(const float4*)(X + (size_t)(row0+m)*ldx + k0 + k4);
        unsigned short h0,h1,h2,h3,l0,l1,l2,l3;
        split1(v.x,h0,l0); split1(v.y,h1,l1); split1(v.z,h2,l2); split1(v.w,h3,l3);
        uint2 hp = make_uint2((uint32_t)h0 | ((uint32_t)h1<<16), (uint32_t)h2 | ((uint32_t)h3<<16));
        uint2 lp = make_uint2((uint32_t)l0 | ((uint32_t)l1<<16), (uint32_t)l2 | ((uint32_t)l3<<16));
        *(uint2*)(dh + m*48 + k4) = hp;
        *(uint2*)(dl + m*48 + k4) = lp;
    }
}

// same, but multiply by inv-row-sum and write normalized value back in place
__device__ __forceinline__ void load_a_split_norm(int tid, float* A, int ldx,
                                                  int row0, int k0, bf16* dh, bf16* dl,
                                                  const float* __restrict__ inv){
    #pragma unroll
    for (int i = 0; i < 4; i++) {
        int e = tid + i*256;
        int m = e >> 3, k4 = (e & 7) << 2;
        float* gp = A + (size_t)(row0+m)*ldx + k0 + k4;
        float4 v = *(const float4*)gp;
        float iv = inv[m];
        v.x *= iv; v.y *= iv; v.z *= iv; v.w *= iv;
        *(float4*)gp = v;                          // normalized attn output
        unsigned short h0,h1,h2,h3,l0,l1,l2,l3;
        split1(v.x,h0,l0); split1(v.y,h1,l1); split1(v.z,h2,l2); split1(v.w,h3,l3);
        uint2 hp = make_uint2((uint32_t)h0 | ((uint32_t)h1<<16), (uint32_t)h2 | ((uint32_t)h3<<16));
        uint2 lp = make_uint2((uint32_t)l0 | ((uint32_t)l1<<16), (uint32_t)l2 | ((uint32_t)l3<<16));
        *(uint2*)(dh + m*48 + k4) = hp;
        *(uint2*)(dl + m*48 + k4) = lp;
    }
}

// bf16 [128 rows x 32 k] copy, pitch 48
__device__ __forceinline__ void load_rows_bf16(int tid, const bf16* __restrict__ G, int ld,
                                               int row0, int k0, bf16* dst){
    #pragma unroll
    for (int i = 0; i < 2; i++) {
        int e = tid + i*256;
        int rr = e >> 2, o = e & 3;
        uint4 v = *(const uint4*)(G + (size_t)(row0+rr)*ld + k0 + o*8);
        *(uint4*)(dst + rr*48 + o*8) = v;
    }
}

// bf16 [32 rows x 64 n] copy (V tile, row-major), pitch 80
__device__ __forceinline__ void load_v_bf16(int tid, const bf16* __restrict__ G,
                                            int k0, bf16* dst){
    int rr = tid >> 3, o = tid & 7;
    uint4 v = *(const uint4*)(G + (size_t)(k0+rr)*DH_ + o*8);
    *(uint4*)(dst + rr*80 + o*8) = v;
}

// ============================================================================
// Weight split+transpose: W[k][n] fp32 -> W^T hi/lo [n][k] bf16
// ============================================================================
__global__ __launch_bounds__(256) void split_w_kernel(const float* __restrict__ W,
                                                      bf16* __restrict__ oh,
                                                      bf16* __restrict__ ol){
    __shared__ float s[32][33];
    const int bk = blockIdx.x*32, bn = blockIdx.y*32;
    const int tx = threadIdx.x & 31, ty = threadIdx.x >> 5;
    #pragma unroll
    for (int i = 0; i < 4; i++)
        s[ty + i*8][tx] = W[(size_t)(bk + ty + i*8)*D_ + bn + tx];
    __syncthreads();
    #pragma unroll
    for (int i = 0; i < 4; i++) {
        float v = s[tx][ty + i*8];
        unsigned short h, l; split1(v, h, l);
        size_t a = (size_t)(bn + ty + i*8)*D_ + bk + tx;
        oh[a] = __ushort_as_bfloat16(h);
        ol[a] = __ushort_as_bfloat16(l);
    }
}

// ============================================================================
// Projection GEMM: C[128x128] = X[M,1024] @ W[1024,1024] + bias
// ============================================================================
template<int MODE>
__global__ __launch_bounds__(256, 2) void proj_mma(
    const float* __restrict__ X,
    const bf16* __restrict__ Wth, const bf16* __restrict__ Wtl,
    const float* __restrict__ bias,
    bf16* __restrict__ outH, bf16* __restrict__ outL, float* __restrict__ outF)
{
    extern __shared__ char sm[];
    bf16* Ah = (bf16*)sm;           // [128][48]
    bf16* Al = Ah + 128*48;
    bf16* Bh = Al + 128*48;
    bf16* Bl = Bh + 128*48;
    const int tid = threadIdx.x, w = tid >> 5, lid = tid & 31;
    const int wm = w >> 2, wn = w & 3;            // 2 x 4
    const int bm = blockIdx.y * 128, bn = blockIdx.x * 128;

    wmma::fragment<wmma::accumulator, 16, 16, 16, float> acc[4][2];
    #pragma unroll
    for (int i = 0; i < 4; i++)
        #pragma unroll
        for (int j = 0; j < 2; j++)
            wmma::fill_fragment(acc[i][j], 0.0f);

    for (int t = 0; t < 32; t++) {
        load_a_split(tid, X, D_, bm, t*32, Ah, Al);
        load_rows_bf16(tid, Wth, D_, bn, t*32, Bh);
        load_rows_bf16(tid, Wtl, D_, bn, t*32, Bl);
        __syncthreads();
        #pragma unroll
        for (int ks = 0; ks < 32; ks += 16) {
            wmma::fragment<wmma::matrix_b, 16, 16, 16, bf16, wmma::col_major> fbh[2], fbl[2];
            #pragma unroll
            for (int j = 0; j < 2; j++) {
                wmma::load_matrix_sync(fbh[j], Bh + (wn*32 + j*16)*48 + ks, 48);
                wmma::load_matrix_sync(fbl[j], Bl + (wn*32 + j*16)*48 + ks, 48);
            }
            #pragma unroll
            for (int i = 0; i < 4; i++) {
                wmma::fragment<wmma::matrix_a, 16, 16, 16, bf16, wmma::row_major> fah, fal;
                wmma::load_matrix_sync(fah, Ah + (wm*64 + i*16)*48 + ks, 48);
                wmma::load_matrix_sync(fal, Al + (wm*64 + i*16)*48 + ks, 48);
                #pragma unroll
                for (int j = 0; j < 2; j++) {
                    wmma::mma_sync(acc[i][j], fah, fbh[j], acc[i][j]);
                    wmma::mma_sync(acc[i][j], fah, fbl[j], acc[i][j]);
                    wmma::mma_sync(acc[i][j], fal, fbh[j], acc[i][j]);
                }
            }
        }
        __syncthreads();
    }

    float* ws = (float*)sm + w * (16*24);
    #pragma unroll
    for (int i = 0; i < 4; i++) {
        #pragma unroll
        for (int j = 0; j < 2; j++) {
            wmma::store_matrix_sync(ws, acc[i][j], 24, wmma::mem_row_major);
            __syncwarp();
            #pragma unroll
            for (int tt = 0; tt < 8; tt++) {
                int e = lid + tt*32, r = e >> 4, c = e & 15;
                int m = bm + wm*64 + i*16 + r;
                int n = bn + wn*32 + j*16 + c;
                float v = ws[r*24 + c] + bias[n];
                if (MODE == 0) {
                    unsigned short hs, ls; split1(v, hs, ls);
                    int bb = m >> 11, l = m & (L_-1), h = n >> 6, dh = n & 63;
                    size_t a = (((size_t)(bb*H_ + h))*L_ + l)*DH_ + dh;
                    outH[a] = __ushort_as_bfloat16(hs);
                    outL[a] = __ushort_as_bfloat16(ls);
                } else {
                    outF[(size_t)m*D_ + n] = v;
                }
            }
            __syncwarp();
        }
    }
}

// ============================================================================
// Scores: writes exp(SCALE * Q@K^T) (unnormalized) + per-row partial sums.
// Deterministic: shuffles + per-(row,warpcol) smem slots, no atomics.
// ============================================================================
__global__ __launch_bounds__(256, 2) void scores_mma(float* __restrict__ attn)
{
    extern __shared__ char sm[];
    bf16* Ah = (bf16*)sm;
    bf16* Al = Ah + 128*48;
    bf16* Bh = Al + 128*48;
    bf16* Bl = Bh + 128*48;
    const int tid = threadIdx.x, w = tid >> 5, lid = tid & 31;
    const int wm = w >> 2, wn = w & 3;
    const int bh = blockIdx.z, bm = blockIdx.y * 128, bn = blockIdx.x * 128;
    const size_t qo = (size_t)bh * L_ * DH_;

    wmma::fragment<wmma::accumulator, 16, 16, 16, float> acc[4][2];
    #pragma unroll
    for (int i = 0; i < 4; i++)
        #pragma unroll
        for (int j = 0; j < 2; j++)
            wmma::fill_fragment(acc[i][j], 0.0f);

    #pragma unroll
    for (int t = 0; t < 2; t++) {
        load_rows_bf16(tid, g_Qh + qo, DH_, bm, t*32, Ah);
        load_rows_bf16(tid, g_Ql + qo, DH_, bm, t*32, Al);
        load_rows_bf16(tid, g_Kh + qo, DH_, bn, t*32, Bh);
        load_rows_bf16(tid, g_Kl + qo, DH_, bn, t*32, Bl);
        __syncthreads();
        #pragma unroll
        for (int ks = 0; ks < 32; ks += 16) {
            wmma::fragment<wmma::matrix_b, 16, 16, 16, bf16, wmma::col_major> fbh[2], fbl[2];
            #pragma unroll
            for (int j = 0; j < 2; j++) {
                wmma::load_matrix_sync(fbh[j], Bh + (wn*32 + j*16)*48 + ks, 48);
                wmma::load_matrix_sync(fbl[j], Bl + (wn*32 + j*16)*48 + ks, 48);
            }
            #pragma unroll
            for (int i = 0; i < 4; i++) {
                wmma::fragment<wmma::matrix_a, 16, 16, 16, bf16, wmma::row_major> fah, fal;
                wmma::load_matrix_sync(fah, Ah + (wm*64 + i*16)*48 + ks, 48);
                wmma::load_matrix_sync(fal, Al + (wm*64 + i*16)*48 + ks, 48);
                #pragma unroll
                for (int j = 0; j < 2; j++) {
                    wmma::mma_sync(acc[i][j], fah, fbh[j], acc[i][j]);
                    wmma::mma_sync(acc[i][j], fah, fbl[j], acc[i][j]);
                    wmma::mma_sync(acc[i][j], fal, fbh[j], acc[i][j]);
                }
            }
        }
        __syncthreads();
    }

    float* ws   = (float*)sm + w * (16*24);      // per-warp 16x16 staging
    float* sums = (float*)sm + 8 * (16*24);      // [128][4] row partial sums
    for (int e = tid; e < 512; e += 256) sums[e] = 0.0f;
    __syncthreads();

    #pragma unroll
    for (int i = 0; i < 4; i++) {
        #pragma unroll
        for (int j = 0; j < 2; j++) {
            wmma::store_matrix_sync(ws, acc[i][j], 24, wmma::mem_row_major);
            __syncwarp();
            #pragma unroll
            for (int tt = 0; tt < 8; tt++) {
                int e = lid + tt*32, r = e >> 4, c = e & 15;
                int m = bm + wm*64 + i*16 + r;
                int n = bn + wn*32 + j*16 + c;
                float ex = __expf(ws[r*24 + c] * SCALE);
                attn[((size_t)bh*L_ + m)*L_ + n] = ex;
                // half-warp (16-lane) reduction -> lanes 0 and 16 hold row sums
                float s2 = ex;
                s2 += __shfl_xor_sync(0xffffffffu, s2, 1);
                s2 += __shfl_xor_sync(0xffffffffu, s2, 2);
                s2 += __shfl_xor_sync(0xffffffffu, s2, 4);
                s2 += __shfl_xor_sync(0xffffffffu, s2, 8);
                if ((lid & 15) == 0)
                    sums[(wm*64 + i*16 + r)*4 + wn] += s2;
            }
            __syncwarp();
        }
    }
    __syncthreads();
    if (tid < 128) {
        float t4 = sums[tid*4] + sums[tid*4+1] + sums[tid*4+2] + sums[tid*4+3];
        g_partial[(((size_t)bh*16 + blockIdx.y)*128 + tid)*16 + blockIdx.x] = t4;
    }
}

// ============================================================================
// PV: normalize exp-attn in place (writes final attn) and O = attn @ V
// ============================================================================
__global__ __launch_bounds__(256, 2) void pv_mma(float* __restrict__ attn)
{
    extern __shared__ char sm[];
    bf16* Ph = (bf16*)sm;            // [128][48]
    bf16* Pl = Ph + 128*48;
    bf16* Vh = Pl + 128*48;          // [32][80]
    bf16* Vl = Vh + 32*80;
    float* inv = (float*)(Vl + 32*80);  // [128]
    const int tid = threadIdx.x, w = tid >> 5, lid = tid & 31;
    const int wm = w >> 1, wn = w & 1;            // 4 x 2
    const int bh = blockIdx.y, bm = blockIdx.x * 128;
    float* A = attn + (size_t)bh * L_ * L_;
    const bf16* Vgh = g_Vh + (size_t)bh * L_ * DH_;
    const bf16* Vgl = g_Vl + (size_t)bh * L_ * DH_;

    if (tid < 128) {
        size_t base = (((size_t)bh*16 + blockIdx.x)*128 + tid)*16;
        float s = 0.0f;
        #pragma unroll
        for (int nt = 0; nt < 16; nt++) s += g_partial[base + nt];
        inv[tid] = 1.0f / s;
    }
    __syncthreads();

    wmma::fragment<wmma::accumulator, 16, 16, 16, float> acc[2][2];
    #pragma unroll
    for (int i = 0; i < 2; i++)
        #pragma unroll
        for (int j = 0; j < 2; j++)
            wmma::fill_fragment(acc[i][j], 0.0f);

    for (int t = 0; t < 64; t++) {
        load_a_split_norm(tid, A, L_, bm, t*32, Ph, Pl, inv);
        load_v_bf16(tid, Vgh, t*32, Vh);
        load_v_bf16(tid, Vgl, t*32, Vl);
        __syncthreads();
        #pragma unroll
        for (int ks = 0; ks < 32; ks += 16) {
            wmma::fragment<wmma::matrix_b, 16, 16, 16, bf16, wmma::row_major> fbh[2], fbl[2];
            #pragma unroll
            for (int j = 0; j < 2; j++) {
                wmma::load_matrix_sync(fbh[j], Vh + ks*80 + wn*32 + j*16, 80);
                wmma::load_matrix_sync(fbl[j], Vl + ks*80 + wn*32 + j*16, 80);
            }
            #pragma unroll
            for (int i = 0; i < 2; i++) {
                wmma::fragment<wmma::matrix_a, 16, 16, 16, bf16, wmma::row_major> fah, fal;
                wmma::load_matrix_sync(fah, Ph + (wm*32 + i*16)*48 + ks, 48);
                wmma::load_matrix_sync(fal, Pl + (wm*32 + i*16)*48 + ks, 48);
                #pragma unroll
                for (int j = 0; j < 2; j++) {
                    wmma::mma_sync(acc[i][j], fah, fbh[j], acc[i][j]);
                    wmma::mma_sync(acc[i][j], fah, fbl[j], acc[i][j]);
                    wmma::mma_sync(acc[i][j], fal, fbh[j], acc[i][j]);
                }
            }
        }
        __syncthreads();
    }

    float* ws = (float*)sm + w * (16*24);
    const int b = bh >> 4, h = bh & 15;
    #pragma unroll
    for (int i = 0; i < 2; i++) {
        #pragma unroll
        for (int j = 0; j < 2; j++) {
            wmma::store_matrix_sync(ws, acc[i][j], 24, wmma::mem_row_major);
            __syncwarp();
            #pragma unroll
            for (int tt = 0; tt < 8; tt++) {
                int e = lid + tt*32, r = e >> 4, c = e & 15;
                int m = bm + wm*32 + i*16 + r;
                int n = wn*32 + j*16 + c;
                g_O[((size_t)(b*L_ + m))*D_ + h*DH_ + n] = ws[r*24 + c];
            }
            __syncwarp();
        }
    }
}

// ============================================================================
extern "C" void kernel_launch(void* const* d_in, const int* in_sizes, int n_in,
                              void* d_out, int out_size)
{
    const float* q  = (const float*)d_in[0];
    const float* k  = (const float*)d_in[1];
    const float* v  = (const float*)d_in[2];
    const float* Wq = (const float*)d_in[3];
    const float* bq = (const float*)d_in[4];
    const float* Wk = (const float*)d_in[5];
    const float* bk = (const float*)d_in[6];
    const float* Wv = (const float*)d_in[7];
    const float* bv = (const float*)d_in[8];
    const float* Wo = (const float*)d_in[9];
    const float* bo = (const float*)d_in[10];
    float* out = (float*)d_out;

    float *pO, *pAttnFb;
    bf16 *pQh,*pQl,*pKh,*pKl,*pVh,*pVl,*pWth,*pWtl;
    cudaGetSymbolAddress((void**)&pO, g_O);
    cudaGetSymbolAddress((void**)&pAttnFb, g_attn_fallback);
    cudaGetSymbolAddress((void**)&pQh, g_Qh);
    cudaGetSymbolAddress((void**)&pQl, g_Ql);
    cudaGetSymbolAddress((void**)&pKh, g_Kh);
    cudaGetSymbolAddress((void**)&pKl, g_Kl);
    cudaGetSymbolAddress((void**)&pVh, g_Vh);
    cudaGetSymbolAddress((void**)&pVl, g_Vl);
    cudaGetSymbolAddress((void**)&pWth, g_Wth);
    cudaGetSymbolAddress((void**)&pWtl, g_Wtl);

    const long long need = (long long)M_ * D_ + (long long)BH_ * L_ * L_;
    float* attn = ((long long)out_size >= need) ? (out + (size_t)M_ * D_) : pAttnFb;

    const int SM_PROJ = 128*48*2*2 * 2;                 // 49152
    const int SM_PV   = 128*48*2*2 + 32*80*2*2 + 512;   // 35328

    cudaFuncSetAttribute(proj_mma<0>, cudaFuncAttributeMaxDynamicSharedMemorySize, SM_PROJ);
    cudaFuncSetAttribute(proj_mma<2>, cudaFuncAttributeMaxDynamicSharedMemorySize, SM_PROJ);
    cudaFuncSetAttribute(scores_mma,  cudaFuncAttributeMaxDynamicSharedMemorySize, SM_PROJ);
    cudaFuncSetAttribute(pv_mma,      cudaFuncAttributeMaxDynamicSharedMemorySize, SM_PV);

    const size_t WSZ = (size_t)D_ * D_;
    dim3 gW(D_/32, D_/32);
    split_w_kernel<<<gW, 256>>>(Wq, pWth + 0*WSZ, pWtl + 0*WSZ);
    split_w_kernel<<<gW, 256>>>(Wk, pWth + 1*WSZ, pWtl + 1*WSZ);
    split_w_kernel<<<gW, 256>>>(Wv, pWth + 2*WSZ, pWtl + 2*WSZ);
    split_w_kernel<<<gW, 256>>>(Wo, pWth + 3*WSZ, pWtl + 3*WSZ);

    dim3 gProj(D_/128, M_/128);   // (8, 64)
    proj_mma<0><<<gProj, 256, SM_PROJ>>>(q, pWth + 0*WSZ, pWtl + 0*WSZ, bq, pQh, pQl, nullptr);
    proj_mma<0><<<gProj, 256, SM_PROJ>>>(k, pWth + 1*WSZ, pWtl + 1*WSZ, bk, pKh, pKl, nullptr);
    proj_mma<0><<<gProj, 256, SM_PROJ>>>(v, pWth + 2*WSZ, pWtl + 2*WSZ, bv, pVh, pVl, nullptr);

    dim3 gS(L_/128, L_/128, BH_); // (16,16,64)
    scores_mma<<<gS, 256, SM_PROJ>>>(attn);

    dim3 gPV(L_/128, BH_);        // (16, 64)
    pv_mma<<<gPV, 256, SM_PV>>>(attn);

    proj_mma<2><<<gProj, 256, SM_PROJ>>>(pO, pWth + 3*WSZ, pWtl + 3*WSZ, bo, nullptr, nullptr, out);
}

// round 7
// speedup vs baseline: 1.2936x; 1.2936x over previous
#include <cuda_runtime.h>
#include <cuda_bf16.h>
#include <cuda_pipeline.h>
#include <mma.h>
#include <stdint.h>

using namespace nvcuda;

#define B_  4
#define L_  2048
#define D_  1024
#define H_  16
#define DH_ 64
#define M_  (B_*L_)
#define BH_ (B_*H_)
#define SCALE 0.5f

typedef __nv_bfloat16 bf16;

// ---------------- static scratch ----------------
__device__ float g_O[(size_t)M_*D_];
__device__ bf16 g_Qh[(size_t)BH_*L_*DH_];
__device__ bf16 g_Ql[(size_t)BH_*L_*DH_];
__device__ bf16 g_Kh[(size_t)BH_*L_*DH_];
__device__ bf16 g_Kl[(size_t)BH_*L_*DH_];
__device__ bf16 g_Vh[(size_t)BH_*L_*DH_];
__device__ bf16 g_Vl[(size_t)BH_*L_*DH_];
__device__ bf16 g_Wth[4][(size_t)D_*D_];    // W^T hi: [n][k]
__device__ bf16 g_Wtl[4][(size_t)D_*D_];
__device__ float g_attn_fallback[(size_t)BH_*L_*L_];

__device__ __forceinline__ void split1(float x, unsigned short& h, unsigned short& l){
    bf16 hb = __float2bfloat16(x);
    float r = x - __bfloat162float(hb);
    bf16 lb = __float2bfloat16(r);
    h = __bfloat16_as_ushort(hb);
    l = __bfloat16_as_ushort(lb);
}

// ---- register-prefetch A tile: fp32 [128 x 32] ----
struct ARegs { float4 v[4]; };

__device__ __forceinline__ void fetch_a(ARegs& r, const float* __restrict__ X, int ldx,
                                        int row0, int k0, int tid){
    #pragma unroll
    for (int i = 0; i < 4; i++) {
        int e = tid + i*256;
        int m = e >> 3, k4 = (e & 7) << 2;
        r.v[i] = *(const float4*)(X + (size_t)(row0+m)*ldx + k0 + k4);
    }
}
__device__ __forceinline__ void store_a(const ARegs& r, bf16* dh, bf16* dl, int tid){
    #pragma unroll
    for (int i = 0; i < 4; i++) {
        int e = tid + i*256;
        int m = e >> 3, k4 = (e & 7) << 2;
        unsigned short h0,h1,h2,h3,l0,l1,l2,l3;
        split1(r.v[i].x,h0,l0); split1(r.v[i].y,h1,l1);
        split1(r.v[i].z,h2,l2); split1(r.v[i].w,h3,l3);
        uint2 hp = make_uint2((uint32_t)h0 | ((uint32_t)h1<<16), (uint32_t)h2 | ((uint32_t)h3<<16));
        uint2 lp = make_uint2((uint32_t)l0 | ((uint32_t)l1<<16), (uint32_t)l2 | ((uint32_t)l3<<16));
        *(uint2*)(dh + m*48 + k4) = hp;
        *(uint2*)(dl + m*48 + k4) = lp;
    }
}

// async copy bf16 [128 x 32] tile (pitch 48)
__device__ __forceinline__ void async_b(int tid, const bf16* __restrict__ G, int ld,
                                        int row0, int k0, bf16* dst){
    #pragma unroll
    for (int i = 0; i < 2; i++) {
        int e = tid + i*256;
        int rr = e >> 2, o = e & 3;
        __pipeline_memcpy_async(dst + rr*48 + o*8,
                                G + (size_t)(row0+rr)*ld + k0 + o*8, 16);
    }
}
// async copy bf16 [32 x 64] V tile (pitch 80)
__device__ __forceinline__ void async_v(int tid, const bf16* __restrict__ G,
                                        int k0, bf16* dst){
    int rr = tid >> 3, o = tid & 7;
    __pipeline_memcpy_async(dst + rr*80 + o*8,
                            G + (size_t)(k0+rr)*DH_ + o*8, 16);
}

// plain bf16 [128 x 32] copy (scores kernel, 2 iters only)
__device__ __forceinline__ void load_rows_bf16(int tid, const bf16* __restrict__ G, int ld,
                                               int row0, int k0, bf16* dst){
    #pragma unroll
    for (int i = 0; i < 2; i++) {
        int e = tid + i*256;
        int rr = e >> 2, o = e & 3;
        uint4 v = *(const uint4*)(G + (size_t)(row0+rr)*ld + k0 + o*8);
        *(uint4*)(dst + rr*48 + o*8) = v;
    }
}

// ============================================================================
// Weight split+transpose: W[k][n] fp32 -> W^T hi/lo [n][k] bf16
// ============================================================================
__global__ __launch_bounds__(256) void split_w_kernel(const float* __restrict__ W,
                                                      bf16* __restrict__ oh,
                                                      bf16* __restrict__ ol){
    __shared__ float s[32][33];
    const int bk = blockIdx.x*32, bn = blockIdx.y*32;
    const int tx = threadIdx.x & 31, ty = threadIdx.x >> 5;
    #pragma unroll
    for (int i = 0; i < 4; i++)
        s[ty + i*8][tx] = W[(size_t)(bk + ty + i*8)*D_ + bn + tx];
    __syncthreads();
    #pragma unroll
    for (int i = 0; i < 4; i++) {
        float v = s[tx][ty + i*8];
        unsigned short h, l; split1(v, h, l);
        size_t a = (size_t)(bn + ty + i*8)*D_ + bk + tx;
        oh[a] = __ushort_as_bfloat16(h);
        ol[a] = __ushort_as_bfloat16(l);
    }
}

// ============================================================================
// Projection GEMM: C[128x128] = X[M,1024] @ W[1024,1024] + bias
// Pipelined: B double-buffered via cp.async, A register-prefetched.
// Staged coalesced epilogue. MODE 0: head-split hi/lo. MODE 2: fp32 flat.
// ============================================================================
template<int MODE>
__global__ __launch_bounds__(256, 2) void proj_mma(
    const float* __restrict__ X,
    const bf16* __restrict__ Wth, const bf16* __restrict__ Wtl,
    const float* __restrict__ bias,
    bf16* __restrict__ outH, bf16* __restrict__ outL, float* __restrict__ outF)
{
    extern __shared__ char sm[];
    const int BT = 128*48;                // elements per tile
    bf16* Ah  = (bf16*)sm;                // mainloop layout: 6 tiles = 73728 B
    bf16* Al  = Ah + BT;
    bf16* Bh0 = Al + BT;
    bf16* Bl0 = Bh0 + BT;
    bf16* Bh1 = Bl0 + BT;
    bf16* Bl1 = Bh1 + BT;
    const int tid = threadIdx.x, w = tid >> 5, lid = tid & 31;
    const int wm = w >> 2, wn = w & 3;    // 2 x 4
    const int bm = blockIdx.y * 128, bn = blockIdx.x * 128;

    wmma::fragment<wmma::accumulator, 16, 16, 16, float> acc[4][2];
    #pragma unroll
    for (int i = 0; i < 4; i++)
        #pragma unroll
        for (int j = 0; j < 2; j++)
            wmma::fill_fragment(acc[i][j], 0.0f);

    async_b(tid, Wth, D_, bn, 0, Bh0);
    async_b(tid, Wtl, D_, bn, 0, Bl0);
    __pipeline_commit();
    ARegs ra;
    fetch_a(ra, X, D_, bm, 0, tid);

    for (int t = 0; t < 32; t++) {
        bf16* Bhc = (t & 1) ? Bh1 : Bh0;
        bf16* Blc = (t & 1) ? Bl1 : Bl0;
        if (t+1 < 32) {
            bf16* Bhn = (t & 1) ? Bh0 : Bh1;
            bf16* Bln = (t & 1) ? Bl0 : Bl1;
            async_b(tid, Wth, D_, bn, (t+1)*32, Bhn);
            async_b(tid, Wtl, D_, bn, (t+1)*32, Bln);
            __pipeline_commit();
        }
        store_a(ra, Ah, Al, tid);
        if (t+1 < 32) __pipeline_wait_prior(1);
        else          __pipeline_wait_prior(0);
        __syncthreads();
        if (t+1 < 32) fetch_a(ra, X, D_, bm, (t+1)*32, tid);

        #pragma unroll
        for (int ks = 0; ks < 32; ks += 16) {
            wmma::fragment<wmma::matrix_b, 16, 16, 16, bf16, wmma::col_major> fbh[2], fbl[2];
            #pragma unroll
            for (int j = 0; j < 2; j++) {
                wmma::load_matrix_sync(fbh[j], Bhc + (wn*32 + j*16)*48 + ks, 48);
                wmma::load_matrix_sync(fbl[j], Blc + (wn*32 + j*16)*48 + ks, 48);
            }
            #pragma unroll
            for (int i = 0; i < 4; i++) {
                wmma::fragment<wmma::matrix_a, 16, 16, 16, bf16, wmma::row_major> fah, fal;
                wmma::load_matrix_sync(fah, Ah + (wm*64 + i*16)*48 + ks, 48);
                wmma::load_matrix_sync(fal, Al + (wm*64 + i*16)*48 + ks, 48);
                #pragma unroll
                for (int j = 0; j < 2; j++) {
                    wmma::mma_sync(acc[i][j], fah, fbh[j], acc[i][j]);
                    wmma::mma_sync(acc[i][j], fah, fbl[j], acc[i][j]);
                    wmma::mma_sync(acc[i][j], fal, fbh[j], acc[i][j]);
                }
            }
        }
        __syncthreads();
    }

    // -------- staged coalesced epilogue --------
    float* ws = (float*)sm + w * (16*24);             // [0, 12288)
    if (MODE == 0) {
        bf16* SH = (bf16*)(sm + 12288);               // [128][136] bf16 = 34816
        bf16* SL = (bf16*)(sm + 12288 + 34816);
        #pragma unroll
        for (int i = 0; i < 4; i++) {
            #pragma unroll
            for (int j = 0; j < 2; j++) {
                wmma::store_matrix_sync(ws, acc[i][j], 24, wmma::mem_row_major);
                __syncwarp();
                #pragma unroll
                for (int tt = 0; tt < 8; tt++) {
                    int e = lid + tt*32, r = e >> 4, c = e & 15;
                    int row = wm*64 + i*16 + r;
                    int col = wn*32 + j*16 + c;
                    float v = ws[r*24 + c] + bias[bn + col];
                    unsigned short hs, ls; split1(v, hs, ls);
                    SH[row*136 + col] = __ushort_as_bfloat16(hs);
                    SL[row*136 + col] = __ushort_as_bfloat16(ls);
                }
                __syncwarp();
            }
        }
        __syncthreads();
        #pragma unroll
        for (int q = 0; q < 8; q++) {
            int e = tid + q*256;
            int rr = e >> 4, o = e & 15;
            int m = bm + rr, bb = m >> 11, l = m & (L_-1);
            int n0 = bn + o*8, h = n0 >> 6, dh = n0 & 63;
            size_t a = (((size_t)(bb*H_ + h))*L_ + l)*DH_ + dh;
            *(uint4*)(outH + a) = *(uint4*)(&SH[rr*136 + o*8]);
            *(uint4*)(outL + a) = *(uint4*)(&SL[rr*136 + o*8]);
        }
    } else {
        float* SF = (float*)(sm + 12288);             // [128][132] fp32 = 67584
        #pragma unroll
        for (int i = 0; i < 4; i++) {
            #pragma unroll
            for (int j = 0; j < 2; j++) {
                wmma::store_matrix_sync(ws, acc[i][j], 24, wmma::mem_row_major);
                __syncwarp();
                #pragma unroll
                for (int tt = 0; tt < 8; tt++) {
                    int e = lid + tt*32, r = e >> 4, c = e & 15;
                    int row = wm*64 + i*16 + r;
                    int col = wn*32 + j*16 + c;
                    SF[row*132 + col] = ws[r*24 + c] + bias[bn + col];
                }
                __syncwarp();
            }
        }
        __syncthreads();
        #pragma unroll
        for (int q = 0; q < 16; q++) {
            int e = tid + q*256;
            int rr = e >> 5, o = e & 31;
            *(float4*)(outF + (size_t)(bm+rr)*D_ + bn + o*4) = *(float4*)(&SF[rr*132 + o*4]);
        }
    }
}

// ============================================================================
// Scores: attn_raw[bh] = SCALE * Q @ K^T, tile 128x128, K=64 (2 chunks of 32)
// ============================================================================
__global__ __launch_bounds__(256, 2) void scores_mma(float* __restrict__ attn)
{
    extern __shared__ char sm[];
    bf16* Ah = (bf16*)sm;
    bf16* Al = Ah + 128*48;
    bf16* Bh = Al + 128*48;
    bf16* Bl = Bh + 128*48;
    const int tid = threadIdx.x, w = tid >> 5, lid = tid & 31;
    const int wm = w >> 2, wn = w & 3;
    const int bh = blockIdx.z, bm = blockIdx.y * 128, bn = blockIdx.x * 128;
    const size_t qo = (size_t)bh * L_ * DH_;

    wmma::fragment<wmma::accumulator, 16, 16, 16, float> acc[4][2];
    #pragma unroll
    for (int i = 0; i < 4; i++)
        #pragma unroll
        for (int j = 0; j < 2; j++)
            wmma::fill_fragment(acc[i][j], 0.0f);

    #pragma unroll
    for (int t = 0; t < 2; t++) {
        load_rows_bf16(tid, g_Qh + qo, DH_, bm, t*32, Ah);
        load_rows_bf16(tid, g_Ql + qo, DH_, bm, t*32, Al);
        load_rows_bf16(tid, g_Kh + qo, DH_, bn, t*32, Bh);
        load_rows_bf16(tid, g_Kl + qo, DH_, bn, t*32, Bl);
        __syncthreads();
        #pragma unroll
        for (int ks = 0; ks < 32; ks += 16) {
            wmma::fragment<wmma::matrix_b, 16, 16, 16, bf16, wmma::col_major> fbh[2], fbl[2];
            #pragma unroll
            for (int j = 0; j < 2; j++) {
                wmma::load_matrix_sync(fbh[j], Bh + (wn*32 + j*16)*48 + ks, 48);
                wmma::load_matrix_sync(fbl[j], Bl + (wn*32 + j*16)*48 + ks, 48);
            }
            #pragma unroll
            for (int i = 0; i < 4; i++) {
                wmma::fragment<wmma::matrix_a, 16, 16, 16, bf16, wmma::row_major> fah, fal;
                wmma::load_matrix_sync(fah, Ah + (wm*64 + i*16)*48 + ks, 48);
                wmma::load_matrix_sync(fal, Al + (wm*64 + i*16)*48 + ks, 48);
                #pragma unroll
                for (int j = 0; j < 2; j++) {
                    wmma::mma_sync(acc[i][j], fah, fbh[j], acc[i][j]);
                    wmma::mma_sync(acc[i][j], fah, fbl[j], acc[i][j]);
                    wmma::mma_sync(acc[i][j], fal, fbh[j], acc[i][j]);
                }
            }
        }
        __syncthreads();
    }

    float* ws = (float*)sm + w * (16*24);
    #pragma unroll
    for (int i = 0; i < 4; i++) {
        #pragma unroll
        for (int j = 0; j < 2; j++) {
            wmma::store_matrix_sync(ws, acc[i][j], 24, wmma::mem_row_major);
            __syncwarp();
            #pragma unroll
            for (int tt = 0; tt < 8; tt++) {
                int e = lid + tt*32, r = e >> 4, c = e & 15;
                int m = bm + wm*64 + i*16 + r;
                int n = bn + wn*32 + j*16 + c;
                attn[((size_t)bh*L_ + m)*L_ + n] = ws[r*24 + c] * SCALE;
            }
            __syncwarp();
        }
    }
}

// ============================================================================
// Softmax, one block per row, float4 vectorized
// ============================================================================
__global__ __launch_bounds__(256) void softmax_kernel(float* __restrict__ attn)
{
    float4* p = (float4*)(attn + (size_t)blockIdx.x * L_);   // 512 float4
    const int t = threadIdx.x;
    float4 a = p[t], b = p[t + 256];
    float m = fmaxf(fmaxf(fmaxf(a.x,a.y),fmaxf(a.z,a.w)),
                    fmaxf(fmaxf(b.x,b.y),fmaxf(b.z,b.w)));
    #pragma unroll
    for (int o = 16; o; o >>= 1) m = fmaxf(m, __shfl_xor_sync(0xffffffffu, m, o));
    __shared__ float redm[8], reds[8];
    if ((t & 31) == 0) redm[t >> 5] = m;
    __syncthreads();
    float bm = redm[0];
    #pragma unroll
    for (int q = 1; q < 8; q++) bm = fmaxf(bm, redm[q]);
    a.x = __expf(a.x - bm); a.y = __expf(a.y - bm);
    a.z = __expf(a.z - bm); a.w = __expf(a.w - bm);
    b.x = __expf(b.x - bm); b.y = __expf(b.y - bm);
    b.z = __expf(b.z - bm); b.w = __expf(b.w - bm);
    float s = a.x + a.y + a.z + a.w + b.x + b.y + b.z + b.w;
    #pragma unroll
    for (int o = 16; o; o >>= 1) s += __shfl_xor_sync(0xffffffffu, s, o);
    if ((t & 31) == 0) reds[t >> 5] = s;
    __syncthreads();
    float bs = 0.f;
    #pragma unroll
    for (int q = 0; q < 8; q++) bs += reds[q];
    float inv = 1.0f / bs;
    a.x *= inv; a.y *= inv; a.z *= inv; a.w *= inv;
    b.x *= inv; b.y *= inv; b.z *= inv; b.w *= inv;
    p[t] = a; p[t + 256] = b;
}

// ============================================================================
// PV: O[128x64] = attn[128x2048] @ V[2048x64]. Pipelined + staged epilogue.
// ============================================================================
__global__ __launch_bounds__(256, 2) void pv_mma(const float* __restrict__ attn)
{
    extern __shared__ char sm[];
    bf16* Ph  = (bf16*)sm;               // [128][48]
    bf16* Pl  = Ph + 128*48;
    bf16* Vh0 = Pl + 128*48;             // [32][80]
    bf16* Vl0 = Vh0 + 32*80;
    bf16* Vh1 = Vl0 + 32*80;
    bf16* Vl1 = Vh1 + 32*80;
    const int tid = threadIdx.x, w = tid >> 5, lid = tid & 31;
    const int wm = w >> 1, wn = w & 1;            // 4 x 2
    const int bh = blockIdx.y, bm = blockIdx.x * 128;
    const float* A = attn + (size_t)bh * L_ * L_;
    const bf16* Vgh = g_Vh + (size_t)bh * L_ * DH_;
    const bf16* Vgl = g_Vl + (size_t)bh * L_ * DH_;

    wmma::fragment<wmma::accumulator, 16, 16, 16, float> acc[2][2];
    #pragma unroll
    for (int i = 0; i < 2; i++)
        #pragma unroll
        for (int j = 0; j < 2; j++)
            wmma::fill_fragment(acc[i][j], 0.0f);

    async_v(tid, Vgh, 0, Vh0);
    async_v(tid, Vgl, 0, Vl0);
    __pipeline_commit();
    ARegs ra;
    fetch_a(ra, A, L_, bm, 0, tid);

    for (int t = 0; t < 64; t++) {
        bf16* Vhc = (t & 1) ? Vh1 : Vh0;
        bf16* Vlc = (t & 1) ? Vl1 : Vl0;
        if (t+1 < 64) {
            bf16* Vhn = (t & 1) ? Vh0 : Vh1;
            bf16* Vln = (t & 1) ? Vl0 : Vl1;
            async_v(tid, Vgh, (t+1)*32, Vhn);
            async_v(tid, Vgl, (t+1)*32, Vln);
            __pipeline_commit();
        }
        store_a(ra, Ph, Pl, tid);
        if (t+1 < 64) __pipeline_wait_prior(1);
        else          __pipeline_wait_prior(0);
        __syncthreads();
        if (t+1 < 64) fetch_a(ra, A, L_, bm, (t+1)*32, tid);

        #pragma unroll
        for (int ks = 0; ks < 32; ks += 16) {
            wmma::fragment<wmma::matrix_b, 16, 16, 16, bf16, wmma::row_major> fbh[2], fbl[2];
            #pragma unroll
            for (int j = 0; j < 2; j++) {
                wmma::load_matrix_sync(fbh[j], Vhc + ks*80 + wn*32 + j*16, 80);
                wmma::load_matrix_sync(fbl[j], Vlc + ks*80 + wn*32 + j*16, 80);
            }
            #pragma unroll
            for (int i = 0; i < 2; i++) {
                wmma::fragment<wmma::matrix_a, 16, 16, 16, bf16, wmma::row_major> fah, fal;
                wmma::load_matrix_sync(fah, Ph + (wm*32 + i*16)*48 + ks, 48);
                wmma::load_matrix_sync(fal, Pl + (wm*32 + i*16)*48 + ks, 48);
                #pragma unroll
                for (int j = 0; j < 2; j++) {
                    wmma::mma_sync(acc[i][j], fah, fbh[j], acc[i][j]);
                    wmma::mma_sync(acc[i][j], fah, fbl[j], acc[i][j]);
                    wmma::mma_sync(acc[i][j], fal, fbh[j], acc[i][j]);
                }
            }
        }
        __syncthreads();
    }

    // staged coalesced epilogue
    float* ws = (float*)sm + w * (16*24);
    float* SO = (float*)(sm + 12288);     // [128][68] fp32 = 34816
    #pragma unroll
    for (int i = 0; i < 2; i++) {
        #pragma unroll
        for (int j = 0; j < 2; j++) {
            wmma::store_matrix_sync(ws, acc[i][j], 24, wmma::mem_row_major);
            __syncwarp();
            #pragma unroll
            for (int tt = 0; tt < 8; tt++) {
                int e = lid + tt*32, r = e >> 4, c = e & 15;
                int row = wm*32 + i*16 + r;
                int col = wn*32 + j*16 + c;
                SO[row*68 + col] = ws[r*24 + c];
            }
            __syncwarp();
        }
    }
    __syncthreads();
    const int b = bh >> 4, h = bh & 15;
    #pragma unroll
    for (int q = 0; q < 8; q++) {
        int e = tid + q*256;
        int rr = e >> 4, o = e & 15;
        *(float4*)(&g_O[((size_t)(b*L_ + bm + rr))*D_ + h*DH_ + o*4]) =
            *(float4*)(&SO[rr*68 + o*4]);
    }
}

// ============================================================================
extern "C" void kernel_launch(void* const* d_in, const int* in_sizes, int n_in,
                              void* d_out, int out_size)
{
    const float* q  = (const float*)d_in[0];
    const float* k  = (const float*)d_in[1];
    const float* v  = (const float*)d_in[2];
    const float* Wq = (const float*)d_in[3];
    const float* bq = (const float*)d_in[4];
    const float* Wk = (const float*)d_in[5];
    const float* bk = (const float*)d_in[6];
    const float* Wv = (const float*)d_in[7];
    const float* bv = (const float*)d_in[8];
    const float* Wo = (const float*)d_in[9];
    const float* bo = (const float*)d_in[10];
    float* out = (float*)d_out;

    float *pO, *pAttnFb;
    bf16 *pQh,*pQl,*pKh,*pKl,*pVh,*pVl,*pWth,*pWtl;
    cudaGetSymbolAddress((void**)&pO, g_O);
    cudaGetSymbolAddress((void**)&pAttnFb, g_attn_fallback);
    cudaGetSymbolAddress((void**)&pQh, g_Qh);
    cudaGetSymbolAddress((void**)&pQl, g_Ql);
    cudaGetSymbolAddress((void**)&pKh, g_Kh);
    cudaGetSymbolAddress((void**)&pKl, g_Kl);
    cudaGetSymbolAddress((void**)&pVh, g_Vh);
    cudaGetSymbolAddress((void**)&pVl, g_Vl);
    cudaGetSymbolAddress((void**)&pWth, g_Wth);
    cudaGetSymbolAddress((void**)&pWtl, g_Wtl);

    const long long need = (long long)M_ * D_ + (long long)BH_ * L_ * L_;
    float* attn = ((long long)out_size >= need) ? (out + (size_t)M_ * D_) : pAttnFb;

    const int SM_PROJ   = 81920;   // mainloop 73728, epilogue 12288+69632
    const int SM_SCORES = 49152;
    const int SM_PV     = 47104;   // mainloop 45056, epilogue 12288+34816

    cudaFuncSetAttribute(proj_mma<0>, cudaFuncAttributeMaxDynamicSharedMemorySize, SM_PROJ);
    cudaFuncSetAttribute(proj_mma<2>, cudaFuncAttributeMaxDynamicSharedMemorySize, SM_PROJ);
    cudaFuncSetAttribute(scores_mma,  cudaFuncAttributeMaxDynamicSharedMemorySize, SM_SCORES);
    cudaFuncSetAttribute(pv_mma,      cudaFuncAttributeMaxDynamicSharedMemorySize, SM_PV);

    const size_t WSZ = (size_t)D_ * D_;
    dim3 gW(D_/32, D_/32);
    split_w_kernel<<<gW, 256>>>(Wq, pWth + 0*WSZ, pWtl + 0*WSZ);
    split_w_kernel<<<gW, 256>>>(Wk, pWth + 1*WSZ, pWtl + 1*WSZ);
    split_w_kernel<<<gW, 256>>>(Wv, pWth + 2*WSZ, pWtl + 2*WSZ);
    split_w_kernel<<<gW, 256>>>(Wo, pWth + 3*WSZ, pWtl + 3*WSZ);

    dim3 gProj(D_/128, M_/128);   // (8, 64)
    proj_mma<0><<<gProj, 256, SM_PROJ>>>(q, pWth + 0*WSZ, pWtl + 0*WSZ, bq, pQh, pQl, nullptr);
    proj_mma<0><<<gProj, 256, SM_PROJ>>>(k, pWth + 1*WSZ, pWtl + 1*WSZ, bk, pKh, pKl, nullptr);
    proj_mma<0><<<gProj, 256, SM_PROJ>>>(v, pWth + 2*WSZ, pWtl + 2*WSZ, bv, pVh, pVl, nullptr);

    dim3 gS(L_/128, L_/128, BH_); // (16,16,64)
    scores_mma<<<gS, 256, SM_SCORES>>>(attn);

    softmax_kernel<<<BH_*L_, 256>>>(attn);

    dim3 gPV(L_/128, BH_);        // (16, 64)
    pv_mma<<<gPV, 256, SM_PV>>>(attn);

    proj_mma<2><<<gProj, 256, SM_PROJ>>>(pO, pWth + 3*WSZ, pWtl + 3*WSZ, bo, nullptr, nullptr, out);
}

// round 8
// speedup vs baseline: 1.6535x; 1.2783x over previous
#include <cuda_runtime.h>
#include <cuda_fp16.h>
#include <cuda_pipeline.h>
#include <mma.h>
#include <stdint.h>

using namespace nvcuda;

#define B_  4
#define L_  2048
#define D_  1024
#define H_  16
#define DH_ 64
#define M_  (B_*L_)
#define BH_ (B_*H_)
#define SCALE 0.5f

typedef __half hf;

// ---------------- static scratch ----------------
__device__ float g_O[(size_t)M_*D_];
__device__ hf g_Qh[(size_t)BH_*L_*DH_];
__device__ hf g_Ql[(size_t)BH_*L_*DH_];
__device__ hf g_Kh[(size_t)BH_*L_*DH_];
__device__ hf g_Kl[(size_t)BH_*L_*DH_];
__device__ hf g_V [(size_t)BH_*L_*DH_];     // plain fp16
__device__ hf g_Wth[4][(size_t)D_*D_];      // W^T hi: [n][k]
__device__ hf g_Wtl[4][(size_t)D_*D_];      // lo used only for Wq, Wk
__device__ float g_attn_fallback[(size_t)BH_*L_*L_];

__device__ __forceinline__ void split1h(float x, unsigned short& h, unsigned short& l){
    hf hb = __float2half_rn(x);
    float r = x - __half2float(hb);
    hf lb = __float2half_rn(r);
    h = __half_as_ushort(hb);
    l = __half_as_ushort(lb);
}

// ---- register-prefetch A tile: fp32 [128 x 32] ----
struct ARegs { float4 v[4]; };

__device__ __forceinline__ void fetch_a(ARegs& r, const float* __restrict__ X, int ldx,
                                        int row0, int k0, int tid){
    #pragma unroll
    for (int i = 0; i < 4; i++) {
        int e = tid + i*256;
        int m = e >> 3, k4 = (e & 7) << 2;
        r.v[i] = *(const float4*)(X + (size_t)(row0+m)*ldx + k0 + k4);
    }
}
// split store (3-term path)
__device__ __forceinline__ void store_a_split(const ARegs& r, hf* dh, hf* dl, int tid){
    #pragma unroll
    for (int i = 0; i < 4; i++) {
        int e = tid + i*256;
        int m = e >> 3, k4 = (e & 7) << 2;
        unsigned short h0,h1,h2,h3,l0,l1,l2,l3;
        split1h(r.v[i].x,h0,l0); split1h(r.v[i].y,h1,l1);
        split1h(r.v[i].z,h2,l2); split1h(r.v[i].w,h3,l3);
        uint2 hp = make_uint2((uint32_t)h0 | ((uint32_t)h1<<16), (uint32_t)h2 | ((uint32_t)h3<<16));
        uint2 lp = make_uint2((uint32_t)l0 | ((uint32_t)l1<<16), (uint32_t)l2 | ((uint32_t)l3<<16));
        *(uint2*)(dh + m*48 + k4) = hp;
        *(uint2*)(dl + m*48 + k4) = lp;
    }
}
// round-only store (1-term path)
__device__ __forceinline__ void store_a_round(const ARegs& r, hf* d, int tid){
    #pragma unroll
    for (int i = 0; i < 4; i++) {
        int e = tid + i*256;
        int m = e >> 3, k4 = (e & 7) << 2;
        __half2 p0 = __floats2half2_rn(r.v[i].x, r.v[i].y);
        __half2 p1 = __floats2half2_rn(r.v[i].z, r.v[i].w);
        uint2 u;
        u.x = *(uint32_t*)&p0;
        u.y = *(uint32_t*)&p1;
        *(uint2*)(d + m*48 + k4) = u;
    }
}

// async copy fp16 [128 x 32] tile (pitch 48)
__device__ __forceinline__ void async_b(int tid, const hf* __restrict__ G, int ld,
                                        int row0, int k0, hf* dst){
    #pragma unroll
    for (int i = 0; i < 2; i++) {
        int e = tid + i*256;
        int rr = e >> 2, o = e & 3;
        __pipeline_memcpy_async(dst + rr*48 + o*8,
                                G + (size_t)(row0+rr)*ld + k0 + o*8, 16);
    }
}
// async copy fp16 [32 x 64] V tile (pitch 80)
__device__ __forceinline__ void async_v(int tid, const hf* __restrict__ G,
                                        int k0, hf* dst){
    int rr = tid >> 3, o = tid & 7;
    __pipeline_memcpy_async(dst + rr*80 + o*8,
                            G + (size_t)(k0+rr)*DH_ + o*8, 16);
}
// plain fp16 [128 x 32] copy
__device__ __forceinline__ void load_rows_h(int tid, const hf* __restrict__ G, int ld,
                                            int row0, int k0, hf* dst){
    #pragma unroll
    for (int i = 0; i < 2; i++) {
        int e = tid + i*256;
        int rr = e >> 2, o = e & 3;
        uint4 v = *(const uint4*)(G + (size_t)(row0+rr)*ld + k0 + o*8);
        *(uint4*)(dst + rr*48 + o*8) = v;
    }
}

// ============================================================================
// Weight split+transpose: W[k][n] fp32 -> W^T hi/lo [n][k] fp16
// ============================================================================
__global__ __launch_bounds__(256) void split_w_kernel(const float* __restrict__ W,
                                                      hf* __restrict__ oh,
                                                      hf* __restrict__ ol){
    __shared__ float s[32][33];
    const int bk = blockIdx.x*32, bn = blockIdx.y*32;
    const int tx = threadIdx.x & 31, ty = threadIdx.x >> 5;
    #pragma unroll
    for (int i = 0; i < 4; i++)
        s[ty + i*8][tx] = W[(size_t)(bk + ty + i*8)*D_ + bn + tx];
    __syncthreads();
    #pragma unroll
    for (int i = 0; i < 4; i++) {
        float v = s[tx][ty + i*8];
        unsigned short h, l; split1h(v, h, l);
        size_t a = (size_t)(bn + ty + i*8)*D_ + bk + tx;
        oh[a] = __ushort_as_half(h);
        ol[a] = __ushort_as_half(l);
    }
}

// ============================================================================
// Projection GEMM: C[128x128] = X[M,1024] @ W[1024,1024] + bias
// MODE 0: 3-term, head-split fp16 hi/lo out (Q,K)
// MODE 1: 1-term, head-split fp16 out (V)
// MODE 2: 1-term, fp32 flat out (final projection)
// ============================================================================
template<int MODE>
__global__ __launch_bounds__(256, 2) void proj_mma(
    const float* __restrict__ X,
    const hf* __restrict__ Wth, const hf* __restrict__ Wtl,
    const float* __restrict__ bias,
    hf* __restrict__ outH, hf* __restrict__ outL, float* __restrict__ outF)
{
    extern __shared__ char sm[];
    const int BT = 128*48;
    hf *Ah, *Al = nullptr, *Bh0, *Bl0 = nullptr, *Bh1, *Bl1 = nullptr;
    if (MODE == 0) {
        Ah = (hf*)sm; Al = Ah + BT; Bh0 = Al + BT; Bl0 = Bh0 + BT; Bh1 = Bl0 + BT; Bl1 = Bh1 + BT;
    } else {
        Ah = (hf*)sm; Bh0 = Ah + BT; Bh1 = Bh0 + BT;
    }
    const int tid = threadIdx.x, w = tid >> 5, lid = tid & 31;
    const int wm = w >> 2, wn = w & 3;    // 2 x 4
    const int bm = blockIdx.y * 128, bn = blockIdx.x * 128;

    wmma::fragment<wmma::accumulator, 16, 16, 16, float> acc[4][2];
    #pragma unroll
    for (int i = 0; i < 4; i++)
        #pragma unroll
        for (int j = 0; j < 2; j++)
            wmma::fill_fragment(acc[i][j], 0.0f);

    async_b(tid, Wth, D_, bn, 0, Bh0);
    if (MODE == 0) async_b(tid, Wtl, D_, bn, 0, Bl0);
    __pipeline_commit();
    ARegs ra;
    fetch_a(ra, X, D_, bm, 0, tid);

    for (int t = 0; t < 32; t++) {
        hf* Bhc = (t & 1) ? Bh1 : Bh0;
        hf* Blc = (t & 1) ? Bl1 : Bl0;
        if (t+1 < 32) {
            hf* Bhn = (t & 1) ? Bh0 : Bh1;
            hf* Bln = (t & 1) ? Bl0 : Bl1;
            async_b(tid, Wth, D_, bn, (t+1)*32, Bhn);
            if (MODE == 0) async_b(tid, Wtl, D_, bn, (t+1)*32, Bln);
            __pipeline_commit();
        }
        if (MODE == 0) store_a_split(ra, Ah, Al, tid);
        else           store_a_round(ra, Ah, tid);
        if (t+1 < 32) __pipeline_wait_prior(1);
        else          __pipeline_wait_prior(0);
        __syncthreads();
        if (t+1 < 32) fetch_a(ra, X, D_, bm, (t+1)*32, tid);

        #pragma unroll
        for (int ks = 0; ks < 32; ks += 16) {
            wmma::fragment<wmma::matrix_b, 16, 16, 16, hf, wmma::col_major> fbh[2], fbl[2];
            #pragma unroll
            for (int j = 0; j < 2; j++) {
                wmma::load_matrix_sync(fbh[j], Bhc + (wn*32 + j*16)*48 + ks, 48);
                if (MODE == 0) wmma::load_matrix_sync(fbl[j], Blc + (wn*32 + j*16)*48 + ks, 48);
            }
            #pragma unroll
            for (int i = 0; i < 4; i++) {
                wmma::fragment<wmma::matrix_a, 16, 16, 16, hf, wmma::row_major> fah, fal;
                wmma::load_matrix_sync(fah, Ah + (wm*64 + i*16)*48 + ks, 48);
                if (MODE == 0) wmma::load_matrix_sync(fal, Al + (wm*64 + i*16)*48 + ks, 48);
                #pragma unroll
                for (int j = 0; j < 2; j++) {
                    wmma::mma_sync(acc[i][j], fah, fbh[j], acc[i][j]);
                    if (MODE == 0) {
                        wmma::mma_sync(acc[i][j], fah, fbl[j], acc[i][j]);
                        wmma::mma_sync(acc[i][j], fal, fbh[j], acc[i][j]);
                    }
                }
            }
        }
        __syncthreads();
    }

    // -------- staged coalesced epilogue --------
    float* ws = (float*)sm + w * (16*24);             // [0, 12288)
    if (MODE == 0) {
        hf* SH = (hf*)(sm + 12288);                   // [128][136] fp16 = 34816
        hf* SL = (hf*)(sm + 12288 + 34816);
        #pragma unroll
        for (int i = 0; i < 4; i++) {
            #pragma unroll
            for (int j = 0; j < 2; j++) {
                wmma::store_matrix_sync(ws, acc[i][j], 24, wmma::mem_row_major);
                __syncwarp();
                #pragma unroll
                for (int tt = 0; tt < 8; tt++) {
                    int e = lid + tt*32, r = e >> 4, c = e & 15;
                    int row = wm*64 + i*16 + r;
                    int col = wn*32 + j*16 + c;
                    float v = ws[r*24 + c] + bias[bn + col];
                    unsigned short hs, ls; split1h(v, hs, ls);
                    SH[row*136 + col] = __ushort_as_half(hs);
                    SL[row*136 + col] = __ushort_as_half(ls);
                }
                __syncwarp();
            }
        }
        __syncthreads();
        #pragma unroll
        for (int q = 0; q < 8; q++) {
            int e = tid + q*256;
            int rr = e >> 4, o = e & 15;
            int m = bm + rr, bb = m >> 11, l = m & (L_-1);
            int n0 = bn + o*8, h = n0 >> 6, dh = n0 & 63;
            size_t a = (((size_t)(bb*H_ + h))*L_ + l)*DH_ + dh;
            *(uint4*)(outH + a) = *(uint4*)(&SH[rr*136 + o*8]);
            *(uint4*)(outL + a) = *(uint4*)(&SL[rr*136 + o*8]);
        }
    } else if (MODE == 1) {
        hf* SH = (hf*)(sm + 12288);
        #pragma unroll
        for (int i = 0; i < 4; i++) {
            #pragma unroll
            for (int j = 0; j < 2; j++) {
                wmma::store_matrix_sync(ws, acc[i][j], 24, wmma::mem_row_major);
                __syncwarp();
                #pragma unroll
                for (int tt = 0; tt < 8; tt++) {
                    int e = lid + tt*32, r = e >> 4, c = e & 15;
                    int row = wm*64 + i*16 + r;
                    int col = wn*32 + j*16 + c;
                    SH[row*136 + col] = __float2half_rn(ws[r*24 + c] + bias[bn + col]);
                }
                __syncwarp();
            }
        }
        __syncthreads();
        #pragma unroll
        for (int q = 0; q < 8; q++) {
            int e = tid + q*256;
            int rr = e >> 4, o = e & 15;
            int m = bm + rr, bb = m >> 11, l = m & (L_-1);
            int n0 = bn + o*8, h = n0 >> 6, dh = n0 & 63;
            size_t a = (((size_t)(bb*H_ + h))*L_ + l)*DH_ + dh;
            *(uint4*)(outH + a) = *(uint4*)(&SH[rr*136 + o*8]);
        }
    } else {
        float* SF = (float*)(sm + 12288);             // [128][132] fp32
        #pragma unroll
        for (int i = 0; i < 4; i++) {
            #pragma unroll
            for (int j = 0; j < 2; j++) {
                wmma::store_matrix_sync(ws, acc[i][j], 24, wmma::mem_row_major);
                __syncwarp();
                #pragma unroll
                for (int tt = 0; tt < 8; tt++) {
                    int e = lid + tt*32, r = e >> 4, c = e & 15;
                    int row = wm*64 + i*16 + r;
                    int col = wn*32 + j*16 + c;
                    SF[row*132 + col] = ws[r*24 + c] + bias[bn + col];
                }
                __syncwarp();
            }
        }
        __syncthreads();
        #pragma unroll
        for (int q = 0; q < 16; q++) {
            int e = tid + q*256;
            int rr = e >> 5, o = e & 31;
            *(float4*)(outF + (size_t)(bm+rr)*D_ + bn + o*4) = *(float4*)(&SF[rr*132 + o*4]);
        }
    }
}

// ============================================================================
// Scores: attn_raw[bh] = SCALE * Q @ K^T, 3-term fp16, K=64 (2 chunks of 32)
// ============================================================================
__global__ __launch_bounds__(256, 2) void scores_mma(float* __restrict__ attn)
{
    extern __shared__ char sm[];
    hf* Ah = (hf*)sm;
    hf* Al = Ah + 128*48;
    hf* Bh = Al + 128*48;
    hf* Bl = Bh + 128*48;
    const int tid = threadIdx.x, w = tid >> 5, lid = tid & 31;
    const int wm = w >> 2, wn = w & 3;
    const int bh = blockIdx.z, bm = blockIdx.y * 128, bn = blockIdx.x * 128;
    const size_t qo = (size_t)bh * L_ * DH_;

    wmma::fragment<wmma::accumulator, 16, 16, 16, float> acc[4][2];
    #pragma unroll
    for (int i = 0; i < 4; i++)
        #pragma unroll
        for (int j = 0; j < 2; j++)
            wmma::fill_fragment(acc[i][j], 0.0f);

    #pragma unroll
    for (int t = 0; t < 2; t++) {
        load_rows_h(tid, g_Qh + qo, DH_, bm, t*32, Ah);
        load_rows_h(tid, g_Ql + qo, DH_, bm, t*32, Al);
        load_rows_h(tid, g_Kh + qo, DH_, bn, t*32, Bh);
        load_rows_h(tid, g_Kl + qo, DH_, bn, t*32, Bl);
        __syncthreads();
        #pragma unroll
        for (int ks = 0; ks < 32; ks += 16) {
            wmma::fragment<wmma::matrix_b, 16, 16, 16, hf, wmma::col_major> fbh[2], fbl[2];
            #pragma unroll
            for (int j = 0; j < 2; j++) {
                wmma::load_matrix_sync(fbh[j], Bh + (wn*32 + j*16)*48 + ks, 48);
                wmma::load_matrix_sync(fbl[j], Bl + (wn*32 + j*16)*48 + ks, 48);
            }
            #pragma unroll
            for (int i = 0; i < 4; i++) {
                wmma::fragment<wmma::matrix_a, 16, 16, 16, hf, wmma::row_major> fah, fal;
                wmma::load_matrix_sync(fah, Ah + (wm*64 + i*16)*48 + ks, 48);
                wmma::load_matrix_sync(fal, Al + (wm*64 + i*16)*48 + ks, 48);
                #pragma unroll
                for (int j = 0; j < 2; j++) {
                    wmma::mma_sync(acc[i][j], fah, fbh[j], acc[i][j]);
                    wmma::mma_sync(acc[i][j], fah, fbl[j], acc[i][j]);
                    wmma::mma_sync(acc[i][j], fal, fbh[j], acc[i][j]);
                }
            }
        }
        __syncthreads();
    }

    float* ws = (float*)sm + w * (16*24);
    #pragma unroll
    for (int i = 0; i < 4; i++) {
        #pragma unroll
        for (int j = 0; j < 2; j++) {
            wmma::store_matrix_sync(ws, acc[i][j], 24, wmma::mem_row_major);
            __syncwarp();
            #pragma unroll
            for (int tt = 0; tt < 8; tt++) {
                int e = lid + tt*32, r = e >> 4, c = e & 15;
                int m = bm + wm*64 + i*16 + r;
                int n = bn + wn*32 + j*16 + c;
                attn[((size_t)bh*L_ + m)*L_ + n] = ws[r*24 + c] * SCALE;
            }
            __syncwarp();
        }
    }
}

// ============================================================================
// Softmax, one block per row, float4 vectorized
// ============================================================================
__global__ __launch_bounds__(256) void softmax_kernel(float* __restrict__ attn)
{
    float4* p = (float4*)(attn + (size_t)blockIdx.x * L_);
    const int t = threadIdx.x;
    float4 a = p[t], b = p[t + 256];
    float m = fmaxf(fmaxf(fmaxf(a.x,a.y),fmaxf(a.z,a.w)),
                    fmaxf(fmaxf(b.x,b.y),fmaxf(b.z,b.w)));
    #pragma unroll
    for (int o = 16; o; o >>= 1) m = fmaxf(m, __shfl_xor_sync(0xffffffffu, m, o));
    __shared__ float redm[8], reds[8];
    if ((t & 31) == 0) redm[t >> 5] = m;
    __syncthreads();
    float bm = redm[0];
    #pragma unroll
    for (int q = 1; q < 8; q++) bm = fmaxf(bm, redm[q]);
    a.x = __expf(a.x - bm); a.y = __expf(a.y - bm);
    a.z = __expf(a.z - bm); a.w = __expf(a.w - bm);
    b.x = __expf(b.x - bm); b.y = __expf(b.y - bm);
    b.z = __expf(b.z - bm); b.w = __expf(b.w - bm);
    float s = a.x + a.y + a.z + a.w + b.x + b.y + b.z + b.w;
    #pragma unroll
    for (int o = 16; o; o >>= 1) s += __shfl_xor_sync(0xffffffffu, s, o);
    if ((t & 31) == 0) reds[t >> 5] = s;
    __syncthreads();
    float bs = 0.f;
    #pragma unroll
    for (int q = 0; q < 8; q++) bs += reds[q];
    float inv = 1.0f / bs;
    a.x *= inv; a.y *= inv; a.z *= inv; a.w *= inv;
    b.x *= inv; b.y *= inv; b.z *= inv; b.w *= inv;
    p[t] = a; p[t + 256] = b;
}

// ============================================================================
// PV: O[128x64] = attn[128x2048] @ V[2048x64], 1-term fp16.
// ============================================================================
__global__ __launch_bounds__(256, 2) void pv_mma(const float* __restrict__ attn)
{
    extern __shared__ char sm[];
    hf* Ph  = (hf*)sm;               // [128][48]
    hf* Vh0 = Ph + 128*48;           // [32][80]
    hf* Vh1 = Vh0 + 32*80;
    const int tid = threadIdx.x, w = tid >> 5, lid = tid & 31;
    const int wm = w >> 1, wn = w & 1;            // 4 x 2
    const int bh = blockIdx.y, bm = blockIdx.x * 128;
    const float* A = attn + (size_t)bh * L_ * L_;
    const hf* Vg = g_V + (size_t)bh * L_ * DH_;

    wmma::fragment<wmma::accumulator, 16, 16, 16, float> acc[2][2];
    #pragma unroll
    for (int i = 0; i < 2; i++)
        #pragma unroll
        for (int j = 0; j < 2; j++)
            wmma::fill_fragment(acc[i][j], 0.0f);

    async_v(tid, Vg, 0, Vh0);
    __pipeline_commit();
    ARegs ra;
    fetch_a(ra, A, L_, bm, 0, tid);

    for (int t = 0; t < 64; t++) {
        hf* Vc = (t & 1) ? Vh1 : Vh0;
        if (t+1 < 64) {
            hf* Vn = (t & 1) ? Vh0 : Vh1;
            async_v(tid, Vg, (t+1)*32, Vn);
            __pipeline_commit();
        }
        store_a_round(ra, Ph, tid);
        if (t+1 < 64) __pipeline_wait_prior(1);
        else          __pipeline_wait_prior(0);
        __syncthreads();
        if (t+1 < 64) fetch_a(ra, A, L_, bm, (t+1)*32, tid);

        #pragma unroll
        for (int ks = 0; ks < 32; ks += 16) {
            wmma::fragment<wmma::matrix_b, 16, 16, 16, hf, wmma::row_major> fbh[2];
            #pragma unroll
            for (int j = 0; j < 2; j++)
                wmma::load_matrix_sync(fbh[j], Vc + ks*80 + wn*32 + j*16, 80);
            #pragma unroll
            for (int i = 0; i < 2; i++) {
                wmma::fragment<wmma::matrix_a, 16, 16, 16, hf, wmma::row_major> fah;
                wmma::load_matrix_sync(fah, Ph + (wm*32 + i*16)*48 + ks, 48);
                #pragma unroll
                for (int j = 0; j < 2; j++)
                    wmma::mma_sync(acc[i][j], fah, fbh[j], acc[i][j]);
            }
        }
        __syncthreads();
    }

    float* ws = (float*)sm + w * (16*24);
    float* SO = (float*)(sm + 12288);     // [128][68] fp32
    #pragma unroll
    for (int i = 0; i < 2; i++) {
        #pragma unroll
        for (int j = 0; j < 2; j++) {
            wmma::store_matrix_sync(ws, acc[i][j], 24, wmma::mem_row_major);
            __syncwarp();
            #pragma unroll
            for (int tt = 0; tt < 8; tt++) {
                int e = lid + tt*32, r = e >> 4, c = e & 15;
                int row = wm*32 + i*16 + r;
                int col = wn*32 + j*16 + c;
                SO[row*68 + col] = ws[r*24 + c];
            }
            __syncwarp();
        }
    }
    __syncthreads();
    const int b = bh >> 4, h = bh & 15;
    #pragma unroll
    for (int q = 0; q < 8; q++) {
        int e = tid + q*256;
        int rr = e >> 4, o = e & 15;
        *(float4*)(&g_O[((size_t)(b*L_ + bm + rr))*D_ + h*DH_ + o*4]) =
            *(float4*)(&SO[rr*68 + o*4]);
    }
}

// ============================================================================
extern "C" void kernel_launch(void* const* d_in, const int* in_sizes, int n_in,
                              void* d_out, int out_size)
{
    const float* q  = (const float*)d_in[0];
    const float* k  = (const float*)d_in[1];
    const float* v  = (const float*)d_in[2];
    const float* Wq = (const float*)d_in[3];
    const float* bq = (const float*)d_in[4];
    const float* Wk = (const float*)d_in[5];
    const float* bk = (const float*)d_in[6];
    const float* Wv = (const float*)d_in[7];
    const float* bv = (const float*)d_in[8];
    const float* Wo = (const float*)d_in[9];
    const float* bo = (const float*)d_in[10];
    float* out = (float*)d_out;

    float *pO, *pAttnFb;
    hf *pQh,*pQl,*pKh,*pKl,*pV,*pWth,*pWtl;
    cudaGetSymbolAddress((void**)&pO, g_O);
    cudaGetSymbolAddress((void**)&pAttnFb, g_attn_fallback);
    cudaGetSymbolAddress((void**)&pQh, g_Qh);
    cudaGetSymbolAddress((void**)&pQl, g_Ql);
    cudaGetSymbolAddress((void**)&pKh, g_Kh);
    cudaGetSymbolAddress((void**)&pKl, g_Kl);
    cudaGetSymbolAddress((void**)&pV,  g_V);
    cudaGetSymbolAddress((void**)&pWth, g_Wth);
    cudaGetSymbolAddress((void**)&pWtl, g_Wtl);

    const long long need = (long long)M_ * D_ + (long long)BH_ * L_ * L_;
    float* attn = ((long long)out_size >= need) ? (out + (size_t)M_ * D_) : pAttnFb;

    const int SM_PROJ0  = 81920;   // 6 tiles mainloop / epi 12288+69632
    const int SM_PROJ1  = 47104;   // 3 tiles mainloop / epi 12288+34816
    const int SM_PROJ2  = 79872;   // 3 tiles mainloop / epi 12288+67584
    const int SM_SCORES = 49152;
    const int SM_PV     = 47104;   // mainloop 22528 / epi 12288+34816

    cudaFuncSetAttribute(proj_mma<0>, cudaFuncAttributeMaxDynamicSharedMemorySize, SM_PROJ0);
    cudaFuncSetAttribute(proj_mma<1>, cudaFuncAttributeMaxDynamicSharedMemorySize, SM_PROJ1);
    cudaFuncSetAttribute(proj_mma<2>, cudaFuncAttributeMaxDynamicSharedMemorySize, SM_PROJ2);
    cudaFuncSetAttribute(scores_mma,  cudaFuncAttributeMaxDynamicSharedMemorySize, SM_SCORES);
    cudaFuncSetAttribute(pv_mma,      cudaFuncAttributeMaxDynamicSharedMemorySize, SM_PV);

    const size_t WSZ = (size_t)D_ * D_;
    dim3 gW(D_/32, D_/32);
    split_w_kernel<<<gW, 256>>>(Wq, pWth + 0*WSZ, pWtl + 0*WSZ);
    split_w_kernel<<<gW, 256>>>(Wk, pWth + 1*WSZ, pWtl + 1*WSZ);
    split_w_kernel<<<gW, 256>>>(Wv, pWth + 2*WSZ, pWtl + 2*WSZ);
    split_w_kernel<<<gW, 256>>>(Wo, pWth + 3*WSZ, pWtl + 3*WSZ);

    dim3 gProj(D_/128, M_/128);   // (8, 64)
    proj_mma<0><<<gProj, 256, SM_PROJ0>>>(q, pWth + 0*WSZ, pWtl + 0*WSZ, bq, pQh, pQl, nullptr);
    proj_mma<0><<<gProj, 256, SM_PROJ0>>>(k, pWth + 1*WSZ, pWtl + 1*WSZ, bk, pKh, pKl, nullptr);
    proj_mma<1><<<gProj, 256, SM_PROJ1>>>(v, pWth + 2*WSZ, nullptr,      bv, pV,  nullptr, nullptr);

    dim3 gS(L_/128, L_/128, BH_); // (16,16,64)
    scores_mma<<<gS, 256, SM_SCORES>>>(attn);

    softmax_kernel<<<BH_*L_, 256>>>(attn);

    dim3 gPV(L_/128, BH_);        // (16, 64)
    pv_mma<<<gPV, 256, SM_PV>>>(attn);

    proj_mma<2><<<gProj, 256, SM_PROJ2>>>(pO, pWth + 3*WSZ, nullptr, bo, nullptr, nullptr, out);
}

// round 9
// speedup vs baseline: 1.7281x; 1.0451x over previous
#include <cuda_runtime.h>
#include <cuda_fp16.h>
#include <cuda_pipeline.h>
#include <mma.h>
#include <stdint.h>

using namespace nvcuda;

#define B_  4
#define L_  2048
#define D_  1024
#define H_  16
#define DH_ 64
#define M_  (B_*L_)
#define BH_ (B_*H_)
#define SCALE 0.5f

typedef __half hf;

// ---------------- static scratch ----------------
__device__ hf g_Oh[(size_t)M_*D_];              // PV output, fp16
__device__ hf g_Qh[(size_t)BH_*L_*DH_];
__device__ hf g_Ql[(size_t)BH_*L_*DH_];
__device__ hf g_Kh[(size_t)BH_*L_*DH_];
__device__ hf g_Kl[(size_t)BH_*L_*DH_];
__device__ hf g_V [(size_t)BH_*L_*DH_];
__device__ hf g_attnh[(size_t)BH_*L_*L_];       // fp16 normalized attn copy
__device__ hf g_Wth[4][(size_t)D_*D_];          // W^T hi: [n][k]
__device__ hf g_Wtl[4][(size_t)D_*D_];          // lo used only for Wq, Wk
__device__ float g_attn_fallback[(size_t)BH_*L_*L_];

__device__ __forceinline__ void split1h(float x, unsigned short& h, unsigned short& l){
    hf hb = __float2half_rn(x);
    float r = x - __half2float(hb);
    hf lb = __float2half_rn(r);
    h = __half_as_ushort(hb);
    l = __half_as_ushort(lb);
}

// ---- register-prefetch A tile: fp32 [128 x 32] ----
struct ARegs { float4 v[4]; };

__device__ __forceinline__ void fetch_a(ARegs& r, const float* __restrict__ X, int ldx,
                                        int row0, int k0, int tid){
    #pragma unroll
    for (int i = 0; i < 4; i++) {
        int e = tid + i*256;
        int m = e >> 3, k4 = (e & 7) << 2;
        r.v[i] = *(const float4*)(X + (size_t)(row0+m)*ldx + k0 + k4);
    }
}
__device__ __forceinline__ void store_a_split(const ARegs& r, hf* dh, hf* dl, int tid){
    #pragma unroll
    for (int i = 0; i < 4; i++) {
        int e = tid + i*256;
        int m = e >> 3, k4 = (e & 7) << 2;
        unsigned short h0,h1,h2,h3,l0,l1,l2,l3;
        split1h(r.v[i].x,h0,l0); split1h(r.v[i].y,h1,l1);
        split1h(r.v[i].z,h2,l2); split1h(r.v[i].w,h3,l3);
        uint2 hp = make_uint2((uint32_t)h0 | ((uint32_t)h1<<16), (uint32_t)h2 | ((uint32_t)h3<<16));
        uint2 lp = make_uint2((uint32_t)l0 | ((uint32_t)l1<<16), (uint32_t)l2 | ((uint32_t)l3<<16));
        *(uint2*)(dh + m*48 + k4) = hp;
        *(uint2*)(dl + m*48 + k4) = lp;
    }
}
__device__ __forceinline__ void store_a_round(const ARegs& r, hf* d, int tid){
    #pragma unroll
    for (int i = 0; i < 4; i++) {
        int e = tid + i*256;
        int m = e >> 3, k4 = (e & 7) << 2;
        __half2 p0 = __floats2half2_rn(r.v[i].x, r.v[i].y);
        __half2 p1 = __floats2half2_rn(r.v[i].z, r.v[i].w);
        uint2 u;
        u.x = *(uint32_t*)&p0;
        u.y = *(uint32_t*)&p1;
        *(uint2*)(d + m*48 + k4) = u;
    }
}

// async copy fp16 [128 x 32] tile (pitch 48)
__device__ __forceinline__ void async_b(int tid, const hf* __restrict__ G, int ld,
                                        int row0, int k0, hf* dst){
    #pragma unroll
    for (int i = 0; i < 2; i++) {
        int e = tid + i*256;
        int rr = e >> 2, o = e & 3;
        __pipeline_memcpy_async(dst + rr*48 + o*8,
                                G + (size_t)(row0+rr)*ld + k0 + o*8, 16);
    }
}
// async copy fp16 [32 x 64] V tile (pitch 80)
__device__ __forceinline__ void async_v(int tid, const hf* __restrict__ G,
                                        int k0, hf* dst){
    int rr = tid >> 3, o = tid & 7;
    __pipeline_memcpy_async(dst + rr*80 + o*8,
                            G + (size_t)(k0+rr)*DH_ + o*8, 16);
}
// plain fp16 [128 x 32] copy
__device__ __forceinline__ void load_rows_h(int tid, const hf* __restrict__ G, int ld,
                                            int row0, int k0, hf* dst){
    #pragma unroll
    for (int i = 0; i < 2; i++) {
        int e = tid + i*256;
        int rr = e >> 2, o = e & 3;
        uint4 v = *(const uint4*)(G + (size_t)(row0+rr)*ld + k0 + o*8);
        *(uint4*)(dst + rr*48 + o*8) = v;
    }
}

// ============================================================================
// Weight split+transpose
// ============================================================================
__global__ __launch_bounds__(256) void split_w_kernel(const float* __restrict__ W,
                                                      hf* __restrict__ oh,
                                                      hf* __restrict__ ol){
    __shared__ float s[32][33];
    const int bk = blockIdx.x*32, bn = blockIdx.y*32;
    const int tx = threadIdx.x & 31, ty = threadIdx.x >> 5;
    #pragma unroll
    for (int i = 0; i < 4; i++)
        s[ty + i*8][tx] = W[(size_t)(bk + ty + i*8)*D_ + bn + tx];
    __syncthreads();
    #pragma unroll
    for (int i = 0; i < 4; i++) {
        float v = s[tx][ty + i*8];
        unsigned short h, l; split1h(v, h, l);
        size_t a = (size_t)(bn + ty + i*8)*D_ + bk + tx;
        oh[a] = __ushort_as_half(h);
        ol[a] = __ushort_as_half(l);
    }
}

// ============================================================================
// Q+K projections fused via blockIdx.z (3-term fp16, head-split hi/lo out)
// ============================================================================
__global__ __launch_bounds__(256, 2) void proj_qk(
    const float* __restrict__ qin, const float* __restrict__ kin,
    const hf* __restrict__ Wth0, const hf* __restrict__ Wtl0,
    const hf* __restrict__ Wth1, const hf* __restrict__ Wtl1,
    const float* __restrict__ bq, const float* __restrict__ bk,
    hf* __restrict__ Qh, hf* __restrict__ Ql,
    hf* __restrict__ Kh, hf* __restrict__ Kl)
{
    const int z = blockIdx.z;
    const float* X   = z ? kin  : qin;
    const hf* Wth    = z ? Wth1 : Wth0;
    const hf* Wtl    = z ? Wtl1 : Wtl0;
    const float* bias= z ? bk   : bq;
    hf* outH         = z ? Kh   : Qh;
    hf* outL         = z ? Kl   : Ql;

    extern __shared__ char sm[];
    const int BT = 128*48;
    hf* Ah  = (hf*)sm;
    hf* Al  = Ah + BT;
    hf* Bh0 = Al + BT;
    hf* Bl0 = Bh0 + BT;
    hf* Bh1 = Bl0 + BT;
    hf* Bl1 = Bh1 + BT;
    const int tid = threadIdx.x, w = tid >> 5, lid = tid & 31;
    const int wm = w >> 2, wn = w & 3;
    const int bm = blockIdx.y * 128, bn = blockIdx.x * 128;

    wmma::fragment<wmma::accumulator, 16, 16, 16, float> acc[4][2];
    #pragma unroll
    for (int i = 0; i < 4; i++)
        #pragma unroll
        for (int j = 0; j < 2; j++)
            wmma::fill_fragment(acc[i][j], 0.0f);

    async_b(tid, Wth, D_, bn, 0, Bh0);
    async_b(tid, Wtl, D_, bn, 0, Bl0);
    __pipeline_commit();
    ARegs ra;
    fetch_a(ra, X, D_, bm, 0, tid);

    for (int t = 0; t < 32; t++) {
        hf* Bhc = (t & 1) ? Bh1 : Bh0;
        hf* Blc = (t & 1) ? Bl1 : Bl0;
        if (t+1 < 32) {
            hf* Bhn = (t & 1) ? Bh0 : Bh1;
            hf* Bln = (t & 1) ? Bl0 : Bl1;
            async_b(tid, Wth, D_, bn, (t+1)*32, Bhn);
            async_b(tid, Wtl, D_, bn, (t+1)*32, Bln);
            __pipeline_commit();
        }
        store_a_split(ra, Ah, Al, tid);
        if (t+1 < 32) __pipeline_wait_prior(1);
        else          __pipeline_wait_prior(0);
        __syncthreads();
        if (t+1 < 32) fetch_a(ra, X, D_, bm, (t+1)*32, tid);

        #pragma unroll
        for (int ks = 0; ks < 32; ks += 16) {
            wmma::fragment<wmma::matrix_b, 16, 16, 16, hf, wmma::col_major> fbh[2], fbl[2];
            #pragma unroll
            for (int j = 0; j < 2; j++) {
                wmma::load_matrix_sync(fbh[j], Bhc + (wn*32 + j*16)*48 + ks, 48);
                wmma::load_matrix_sync(fbl[j], Blc + (wn*32 + j*16)*48 + ks, 48);
            }
            #pragma unroll
            for (int i = 0; i < 4; i++) {
                wmma::fragment<wmma::matrix_a, 16, 16, 16, hf, wmma::row_major> fah, fal;
                wmma::load_matrix_sync(fah, Ah + (wm*64 + i*16)*48 + ks, 48);
                wmma::load_matrix_sync(fal, Al + (wm*64 + i*16)*48 + ks, 48);
                #pragma unroll
                for (int j = 0; j < 2; j++) {
                    wmma::mma_sync(acc[i][j], fah, fbh[j], acc[i][j]);
                    wmma::mma_sync(acc[i][j], fah, fbl[j], acc[i][j]);
                    wmma::mma_sync(acc[i][j], fal, fbh[j], acc[i][j]);
                }
            }
        }
        __syncthreads();
    }

    float* ws = (float*)sm + w * (16*24);
    hf* SH = (hf*)(sm + 12288);
    hf* SL = (hf*)(sm + 12288 + 34816);
    #pragma unroll
    for (int i = 0; i < 4; i++) {
        #pragma unroll
        for (int j = 0; j < 2; j++) {
            wmma::store_matrix_sync(ws, acc[i][j], 24, wmma::mem_row_major);
            __syncwarp();
            #pragma unroll
            for (int tt = 0; tt < 8; tt++) {
                int e = lid + tt*32, r = e >> 4, c = e & 15;
                int row = wm*64 + i*16 + r;
                int col = wn*32 + j*16 + c;
                float v = ws[r*24 + c] + bias[bn + col];
                unsigned short hs, ls; split1h(v, hs, ls);
                SH[row*136 + col] = __ushort_as_half(hs);
                SL[row*136 + col] = __ushort_as_half(ls);
            }
            __syncwarp();
        }
    }
    __syncthreads();
    #pragma unroll
    for (int q = 0; q < 8; q++) {
        int e = tid + q*256;
        int rr = e >> 4, o = e & 15;
        int m = bm + rr, bb = m >> 11, l = m & (L_-1);
        int n0 = bn + o*8, h = n0 >> 6, dh = n0 & 63;
        size_t a = (((size_t)(bb*H_ + h))*L_ + l)*DH_ + dh;
        *(uint4*)(outH + a) = *(uint4*)(&SH[rr*136 + o*8]);
        *(uint4*)(outL + a) = *(uint4*)(&SL[rr*136 + o*8]);
    }
}

// ============================================================================
// V projection (1-term, head-split fp16 out)
// ============================================================================
__global__ __launch_bounds__(256, 2) void proj_v(
    const float* __restrict__ X,
    const hf* __restrict__ Wth, const float* __restrict__ bias,
    hf* __restrict__ outH)
{
    extern __shared__ char sm[];
    const int BT = 128*48;
    hf* Ah  = (hf*)sm;
    hf* Bh0 = Ah + BT;
    hf* Bh1 = Bh0 + BT;
    const int tid = threadIdx.x, w = tid >> 5, lid = tid & 31;
    const int wm = w >> 2, wn = w & 3;
    const int bm = blockIdx.y * 128, bn = blockIdx.x * 128;

    wmma::fragment<wmma::accumulator, 16, 16, 16, float> acc[4][2];
    #pragma unroll
    for (int i = 0; i < 4; i++)
        #pragma unroll
        for (int j = 0; j < 2; j++)
            wmma::fill_fragment(acc[i][j], 0.0f);

    async_b(tid, Wth, D_, bn, 0, Bh0);
    __pipeline_commit();
    ARegs ra;
    fetch_a(ra, X, D_, bm, 0, tid);

    for (int t = 0; t < 32; t++) {
        hf* Bhc = (t & 1) ? Bh1 : Bh0;
        if (t+1 < 32) {
            hf* Bhn = (t & 1) ? Bh0 : Bh1;
            async_b(tid, Wth, D_, bn, (t+1)*32, Bhn);
            __pipeline_commit();
        }
        store_a_round(ra, Ah, tid);
        if (t+1 < 32) __pipeline_wait_prior(1);
        else          __pipeline_wait_prior(0);
        __syncthreads();
        if (t+1 < 32) fetch_a(ra, X, D_, bm, (t+1)*32, tid);

        #pragma unroll
        for (int ks = 0; ks < 32; ks += 16) {
            wmma::fragment<wmma::matrix_b, 16, 16, 16, hf, wmma::col_major> fbh[2];
            #pragma unroll
            for (int j = 0; j < 2; j++)
                wmma::load_matrix_sync(fbh[j], Bhc + (wn*32 + j*16)*48 + ks, 48);
            #pragma unroll
            for (int i = 0; i < 4; i++) {
                wmma::fragment<wmma::matrix_a, 16, 16, 16, hf, wmma::row_major> fah;
                wmma::load_matrix_sync(fah, Ah + (wm*64 + i*16)*48 + ks, 48);
                #pragma unroll
                for (int j = 0; j < 2; j++)
                    wmma::mma_sync(acc[i][j], fah, fbh[j], acc[i][j]);
            }
        }
        __syncthreads();
    }

    float* ws = (float*)sm + w * (16*24);
    hf* SH = (hf*)(sm + 12288);
    #pragma unroll
    for (int i = 0; i < 4; i++) {
        #pragma unroll
        for (int j = 0; j < 2; j++) {
            wmma::store_matrix_sync(ws, acc[i][j], 24, wmma::mem_row_major);
            __syncwarp();
            #pragma unroll
            for (int tt = 0; tt < 8; tt++) {
                int e = lid + tt*32, r = e >> 4, c = e & 15;
                int row = wm*64 + i*16 + r;
                int col = wn*32 + j*16 + c;
                SH[row*136 + col] = __float2half_rn(ws[r*24 + c] + bias[bn + col]);
            }
            __syncwarp();
        }
    }
    __syncthreads();
    #pragma unroll
    for (int q = 0; q < 8; q++) {
        int e = tid + q*256;
        int rr = e >> 4, o = e & 15;
        int m = bm + rr, bb = m >> 11, l = m & (L_-1);
        int n0 = bn + o*8, h = n0 >> 6, dh = n0 & 63;
        size_t a = (((size_t)(bb*H_ + h))*L_ + l)*DH_ + dh;
        *(uint4*)(outH + a) = *(uint4*)(&SH[rr*136 + o*8]);
    }
}

// ============================================================================
// Scores: attn_raw = SCALE * Q @ K^T, 3-term fp16
// ============================================================================
__global__ __launch_bounds__(256, 2) void scores_mma(float* __restrict__ attn)
{
    extern __shared__ char sm[];
    hf* Ah = (hf*)sm;
    hf* Al = Ah + 128*48;
    hf* Bh = Al + 128*48;
    hf* Bl = Bh + 128*48;
    const int tid = threadIdx.x, w = tid >> 5, lid = tid & 31;
    const int wm = w >> 2, wn = w & 3;
    const int bh = blockIdx.z, bm = blockIdx.y * 128, bn = blockIdx.x * 128;
    const size_t qo = (size_t)bh * L_ * DH_;

    wmma::fragment<wmma::accumulator, 16, 16, 16, float> acc[4][2];
    #pragma unroll
    for (int i = 0; i < 4; i++)
        #pragma unroll
        for (int j = 0; j < 2; j++)
            wmma::fill_fragment(acc[i][j], 0.0f);

    #pragma unroll
    for (int t = 0; t < 2; t++) {
        load_rows_h(tid, g_Qh + qo, DH_, bm, t*32, Ah);
        load_rows_h(tid, g_Ql + qo, DH_, bm, t*32, Al);
        load_rows_h(tid, g_Kh + qo, DH_, bn, t*32, Bh);
        load_rows_h(tid, g_Kl + qo, DH_, bn, t*32, Bl);
        __syncthreads();
        #pragma unroll
        for (int ks = 0; ks < 32; ks += 16) {
            wmma::fragment<wmma::matrix_b, 16, 16, 16, hf, wmma::col_major> fbh[2], fbl[2];
            #pragma unroll
            for (int j = 0; j < 2; j++) {
                wmma::load_matrix_sync(fbh[j], Bh + (wn*32 + j*16)*48 + ks, 48);
                wmma::load_matrix_sync(fbl[j], Bl + (wn*32 + j*16)*48 + ks, 48);
            }
            #pragma unroll
            for (int i = 0; i < 4; i++) {
                wmma::fragment<wmma::matrix_a, 16, 16, 16, hf, wmma::row_major> fah, fal;
                wmma::load_matrix_sync(fah, Ah + (wm*64 + i*16)*48 + ks, 48);
                wmma::load_matrix_sync(fal, Al + (wm*64 + i*16)*48 + ks, 48);
                #pragma unroll
                for (int j = 0; j < 2; j++) {
                    wmma::mma_sync(acc[i][j], fah, fbh[j], acc[i][j]);
                    wmma::mma_sync(acc[i][j], fah, fbl[j], acc[i][j]);
                    wmma::mma_sync(acc[i][j], fal, fbh[j], acc[i][j]);
                }
            }
        }
        __syncthreads();
    }

    float* ws = (float*)sm + w * (16*24);
    #pragma unroll
    for (int i = 0; i < 4; i++) {
        #pragma unroll
        for (int j = 0; j < 2; j++) {
            wmma::store_matrix_sync(ws, acc[i][j], 24, wmma::mem_row_major);
            __syncwarp();
            #pragma unroll
            for (int tt = 0; tt < 8; tt++) {
                int e = lid + tt*32, r = e >> 4, c = e & 15;
                int m = bm + wm*64 + i*16 + r;
                int n = bn + wn*32 + j*16 + c;
                attn[((size_t)bh*L_ + m)*L_ + n] = ws[r*24 + c] * SCALE;
            }
            __syncwarp();
        }
    }
}

// ============================================================================
// Softmax: normalizes in place (fp32) and emits fp16 copy for PV
// ============================================================================
__global__ __launch_bounds__(256) void softmax_kernel(float* __restrict__ attn,
                                                      hf* __restrict__ attn16)
{
    float4* p = (float4*)(attn + (size_t)blockIdx.x * L_);
    hf* p16 = attn16 + (size_t)blockIdx.x * L_;
    const int t = threadIdx.x;
    float4 a = p[t], b = p[t + 256];
    float m = fmaxf(fmaxf(fmaxf(a.x,a.y),fmaxf(a.z,a.w)),
                    fmaxf(fmaxf(b.x,b.y),fmaxf(b.z,b.w)));
    #pragma unroll
    for (int o = 16; o; o >>= 1) m = fmaxf(m, __shfl_xor_sync(0xffffffffu, m, o));
    __shared__ float redm[8], reds[8];
    if ((t & 31) == 0) redm[t >> 5] = m;
    __syncthreads();
    float bm = redm[0];
    #pragma unroll
    for (int q = 1; q < 8; q++) bm = fmaxf(bm, redm[q]);
    a.x = __expf(a.x - bm); a.y = __expf(a.y - bm);
    a.z = __expf(a.z - bm); a.w = __expf(a.w - bm);
    b.x = __expf(b.x - bm); b.y = __expf(b.y - bm);
    b.z = __expf(b.z - bm); b.w = __expf(b.w - bm);
    float s = a.x + a.y + a.z + a.w + b.x + b.y + b.z + b.w;
    #pragma unroll
    for (int o = 16; o; o >>= 1) s += __shfl_xor_sync(0xffffffffu, s, o);
    if ((t & 31) == 0) reds[t >> 5] = s;
    __syncthreads();
    float bs = 0.f;
    #pragma unroll
    for (int q = 0; q < 8; q++) bs += reds[q];
    float inv = 1.0f / bs;
    a.x *= inv; a.y *= inv; a.z *= inv; a.w *= inv;
    b.x *= inv; b.y *= inv; b.z *= inv; b.w *= inv;
    p[t] = a; p[t + 256] = b;
    __half2 h0 = __floats2half2_rn(a.x, a.y);
    __half2 h1 = __floats2half2_rn(a.z, a.w);
    __half2 h2 = __floats2half2_rn(b.x, b.y);
    __half2 h3 = __floats2half2_rn(b.z, b.w);
    uint2 u0; u0.x = *(uint32_t*)&h0; u0.y = *(uint32_t*)&h1;
    uint2 u1; u1.x = *(uint32_t*)&h2; u1.y = *(uint32_t*)&h3;
    *(uint2*)(p16 + t*4)         = u0;
    *(uint2*)(p16 + (t + 256)*4) = u1;
}

// ============================================================================
// PV: O[128x64] = attn16[128x2048] @ V[2048x64], all-fp16 async pipeline.
// Writes g_Oh fp16.
// ============================================================================
__global__ __launch_bounds__(256, 2) void pv_mma()
{
    extern __shared__ char sm[];
    hf* Ph0 = (hf*)sm;               // [128][48] = 12288 B
    hf* Ph1 = Ph0 + 128*48;
    hf* Vh0 = Ph1 + 128*48;          // [32][80] = 5120 B
    hf* Vh1 = Vh0 + 32*80;
    const int tid = threadIdx.x, w = tid >> 5, lid = tid & 31;
    const int wm = w >> 1, wn = w & 1;            // 4 x 2
    const int bh = blockIdx.y, bm = blockIdx.x * 128;
    const hf* A16 = g_attnh + (size_t)bh * L_ * L_;
    const hf* Vg = g_V + (size_t)bh * L_ * DH_;

    wmma::fragment<wmma::accumulator, 16, 16, 16, float> acc[2][2];
    #pragma unroll
    for (int i = 0; i < 2; i++)
        #pragma unroll
        for (int j = 0; j < 2; j++)
            wmma::fill_fragment(acc[i][j], 0.0f);

    async_b(tid, A16, L_, bm, 0, Ph0);
    async_v(tid, Vg, 0, Vh0);
    __pipeline_commit();

    for (int t = 0; t < 64; t++) {
        hf* Pc = (t & 1) ? Ph1 : Ph0;
        hf* Vc = (t & 1) ? Vh1 : Vh0;
        if (t+1 < 64) {
            hf* Pn = (t & 1) ? Ph0 : Ph1;
            hf* Vn = (t & 1) ? Vh0 : Vh1;
            async_b(tid, A16, L_, bm, (t+1)*32, Pn);
            async_v(tid, Vg, (t+1)*32, Vn);
            __pipeline_commit();
        }
        if (t+1 < 64) __pipeline_wait_prior(1);
        else          __pipeline_wait_prior(0);
        __syncthreads();

        #pragma unroll
        for (int ks = 0; ks < 32; ks += 16) {
            wmma::fragment<wmma::matrix_b, 16, 16, 16, hf, wmma::row_major> fbh[2];
            #pragma unroll
            for (int j = 0; j < 2; j++)
                wmma::load_matrix_sync(fbh[j], Vc + ks*80 + wn*32 + j*16, 80);
            #pragma unroll
            for (int i = 0; i < 2; i++) {
                wmma::fragment<wmma::matrix_a, 16, 16, 16, hf, wmma::row_major> fah;
                wmma::load_matrix_sync(fah, Pc + (wm*32 + i*16)*48 + ks, 48);
                #pragma unroll
                for (int j = 0; j < 2; j++)
                    wmma::mma_sync(acc[i][j], fah, fbh[j], acc[i][j]);
            }
        }
        __syncthreads();
    }

    float* ws = (float*)sm + w * (16*24);
    hf* SO = (hf*)(sm + 12288);     // [128][72] fp16 = 18432 B
    #pragma unroll
    for (int i = 0; i < 2; i++) {
        #pragma unroll
        for (int j = 0; j < 2; j++) {
            wmma::store_matrix_sync(ws, acc[i][j], 24, wmma::mem_row_major);
            __syncwarp();
            #pragma unroll
            for (int tt = 0; tt < 8; tt++) {
                int e = lid + tt*32, r = e >> 4, c = e & 15;
                int row = wm*32 + i*16 + r;
                int col = wn*32 + j*16 + c;
                SO[row*72 + col] = __float2half_rn(ws[r*24 + c]);
            }
            __syncwarp();
        }
    }
    __syncthreads();
    const int b = bh >> 4, h = bh & 15;
    #pragma unroll
    for (int q = 0; q < 4; q++) {
        int e = tid + q*256;
        int rr = e >> 3, o = e & 7;
        *(uint4*)(&g_Oh[((size_t)(b*L_ + bm + rr))*D_ + h*DH_ + o*8]) =
            *(uint4*)(&SO[rr*72 + o*8]);
    }
}

// ============================================================================
// Output projection: out = g_Oh(fp16) @ Wo + bo, fp32 flat out, fully async
// ============================================================================
__global__ __launch_bounds__(256, 2) void out_proj(
    const hf* __restrict__ Wth, const float* __restrict__ bias,
    float* __restrict__ outF)
{
    extern __shared__ char sm[];
    const int BT = 128*48;
    hf* Ah0 = (hf*)sm;
    hf* Ah1 = Ah0 + BT;
    hf* Bh0 = Ah1 + BT;
    hf* Bh1 = Bh0 + BT;
    const int tid = threadIdx.x, w = tid >> 5, lid = tid & 31;
    const int wm = w >> 2, wn = w & 3;
    const int bm = blockIdx.y * 128, bn = blockIdx.x * 128;

    wmma::fragment<wmma::accumulator, 16, 16, 16, float> acc[4][2];
    #pragma unroll
    for (int i = 0; i < 4; i++)
        #pragma unroll
        for (int j = 0; j < 2; j++)
            wmma::fill_fragment(acc[i][j], 0.0f);

    async_b(tid, g_Oh, D_, bm, 0, Ah0);
    async_b(tid, Wth, D_, bn, 0, Bh0);
    __pipeline_commit();

    for (int t = 0; t < 32; t++) {
        hf* Ac = (t & 1) ? Ah1 : Ah0;
        hf* Bc = (t & 1) ? Bh1 : Bh0;
        if (t+1 < 32) {
            hf* An = (t & 1) ? Ah0 : Ah1;
            hf* Bn = (t & 1) ? Bh0 : Bh1;
            async_b(tid, g_Oh, D_, bm, (t+1)*32, An);
            async_b(tid, Wth, D_, bn, (t+1)*32, Bn);
            __pipeline_commit();
        }
        if (t+1 < 32) __pipeline_wait_prior(1);
        else          __pipeline_wait_prior(0);
        __syncthreads();

        #pragma unroll
        for (int ks = 0; ks < 32; ks += 16) {
            wmma::fragment<wmma::matrix_b, 16, 16, 16, hf, wmma::col_major> fbh[2];
            #pragma unroll
            for (int j = 0; j < 2; j++)
                wmma::load_matrix_sync(fbh[j], Bc + (wn*32 + j*16)*48 + ks, 48);
            #pragma unroll
            for (int i = 0; i < 4; i++) {
                wmma::fragment<wmma::matrix_a, 16, 16, 16, hf, wmma::row_major> fah;
                wmma::load_matrix_sync(fah, Ac + (wm*64 + i*16)*48 + ks, 48);
                #pragma unroll
                for (int j = 0; j < 2; j++)
                    wmma::mma_sync(acc[i][j], fah, fbh[j], acc[i][j]);
            }
        }
        __syncthreads();
    }

    float* ws = (float*)sm + w * (16*24);
    float* SF = (float*)(sm + 12288);
    #pragma unroll
    for (int i = 0; i < 4; i++) {
        #pragma unroll
        for (int j = 0; j < 2; j++) {
            wmma::store_matrix_sync(ws, acc[i][j], 24, wmma::mem_row_major);
            __syncwarp();
            #pragma unroll
            for (int tt = 0; tt < 8; tt++) {
                int e = lid + tt*32, r = e >> 4, c = e & 15;
                int row = wm*64 + i*16 + r;
                int col = wn*32 + j*16 + c;
                SF[row*132 + col] = ws[r*24 + c] + bias[bn + col];
            }
            __syncwarp();
        }
    }
    __syncthreads();
    #pragma unroll
    for (int q = 0; q < 16; q++) {
        int e = tid + q*256;
        int rr = e >> 5, o = e & 31;
        *(float4*)(outF + (size_t)(bm+rr)*D_ + bn + o*4) = *(float4*)(&SF[rr*132 + o*4]);
    }
}

// ============================================================================
extern "C" void kernel_launch(void* const* d_in, const int* in_sizes, int n_in,
                              void* d_out, int out_size)
{
    const float* q  = (const float*)d_in[0];
    const float* k  = (const float*)d_in[1];
    const float* v  = (const float*)d_in[2];
    const float* Wq = (const float*)d_in[3];
    const float* bq = (const float*)d_in[4];
    const float* Wk = (const float*)d_in[5];
    const float* bk = (const float*)d_in[6];
    const float* Wv = (const float*)d_in[7];
    const float* bv = (const float*)d_in[8];
    const float* Wo = (const float*)d_in[9];
    const float* bo = (const float*)d_in[10];
    float* out = (float*)d_out;

    float *pAttnFb;
    hf *pQh,*pQl,*pKh,*pKl,*pV,*pWth,*pWtl,*pAttn16;
    cudaGetSymbolAddress((void**)&pAttnFb, g_attn_fallback);
    cudaGetSymbolAddress((void**)&pQh, g_Qh);
    cudaGetSymbolAddress((void**)&pQl, g_Ql);
    cudaGetSymbolAddress((void**)&pKh, g_Kh);
    cudaGetSymbolAddress((void**)&pKl, g_Kl);
    cudaGetSymbolAddress((void**)&pV,  g_V);
    cudaGetSymbolAddress((void**)&pWth, g_Wth);
    cudaGetSymbolAddress((void**)&pWtl, g_Wtl);
    cudaGetSymbolAddress((void**)&pAttn16, g_attnh);

    const long long need = (long long)M_ * D_ + (long long)BH_ * L_ * L_;
    float* attn = ((long long)out_size >= need) ? (out + (size_t)M_ * D_) : pAttnFb;

    const int SM_QK     = 81920;
    const int SM_V      = 47104;
    const int SM_SCORES = 49152;
    const int SM_PV     = 34816;
    const int SM_OUT    = 79872;

    cudaFuncSetAttribute(proj_qk,    cudaFuncAttributeMaxDynamicSharedMemorySize, SM_QK);
    cudaFuncSetAttribute(proj_v,     cudaFuncAttributeMaxDynamicSharedMemorySize, SM_V);
    cudaFuncSetAttribute(scores_mma, cudaFuncAttributeMaxDynamicSharedMemorySize, SM_SCORES);
    cudaFuncSetAttribute(pv_mma,     cudaFuncAttributeMaxDynamicSharedMemorySize, SM_PV);
    cudaFuncSetAttribute(out_proj,   cudaFuncAttributeMaxDynamicSharedMemorySize, SM_OUT);

    const size_t WSZ = (size_t)D_ * D_;
    dim3 gW(D_/32, D_/32);
    split_w_kernel<<<gW, 256>>>(Wq, pWth + 0*WSZ, pWtl + 0*WSZ);
    split_w_kernel<<<gW, 256>>>(Wk, pWth + 1*WSZ, pWtl + 1*WSZ);
    split_w_kernel<<<gW, 256>>>(Wv, pWth + 2*WSZ, pWtl + 2*WSZ);
    split_w_kernel<<<gW, 256>>>(Wo, pWth + 3*WSZ, pWtl + 3*WSZ);

    dim3 gQK(D_/128, M_/128, 2);  // (8, 64, 2)
    proj_qk<<<gQK, 256, SM_QK>>>(q, k, pWth + 0*WSZ, pWtl + 0*WSZ,
                                 pWth + 1*WSZ, pWtl + 1*WSZ,
                                 bq, bk, pQh, pQl, pKh, pKl);

    dim3 gProj(D_/128, M_/128);   // (8, 64)
    proj_v<<<gProj, 256, SM_V>>>(v, pWth + 2*WSZ, bv, pV);

    dim3 gS(L_/128, L_/128, BH_); // (16,16,64)
    scores_mma<<<gS, 256, SM_SCORES>>>(attn);

    softmax_kernel<<<BH_*L_, 256>>>(attn, pAttn16);

    dim3 gPV(L_/128, BH_);        // (16, 64)
    pv_mma<<<gPV, 256, SM_PV>>>();

    out_proj<<<gProj, 256, SM_OUT>>>(pWth + 3*WSZ, bo, out);
}